// round 1
// baseline (speedup 1.0000x reference)
#include <cuda_runtime.h>

#define NTOK 65536
#define D_IN 768
#define HID  512
#define CBD  256
#define CBK  512

// ---------------- scratch (device globals; no allocations) ----------------
__device__ float g_h[(size_t)NTOK * HID];   // h, then dots (NTOK*512), then h2
__device__ float g_z[(size_t)NTOK * CBD];   // z
__device__ int    g_idxbuf[NTOK];
__device__ float  g_csq[CBK];
__device__ double g_commit;

// ---------------- prep: codebook norms + zero accumulator -----------------
__global__ void prep_kernel(const float* __restrict__ cb) {
    int k = threadIdx.x;           // 512 threads, one code each
    if (k == 0) g_commit = 0.0;
    const float* row = cb + (size_t)k * CBD;
    float s = 0.f;
#pragma unroll 8
    for (int c = 0; c < CBD; c += 4) {
        float4 v = *(const float4*)(row + c);
        s += v.x*v.x + v.y*v.y + v.z*v.z + v.w*v.w;
    }
    g_csq[k] = s;
}

// ---------------- generic tiled SGEMM: C[N,M] = op(A[N,K] @ B + bias) -----
// TRANSB: B physical [M,K] (codebook), logical B[k][m] = Bphys[m][k]
// GATHER: A row r comes from A[rowmap[r]]
template<bool RELU, bool GATHER, bool TRANSB, bool HASBIAS>
__global__ void __launch_bounds__(256) sgemm_kernel(
    const float* __restrict__ A, const float* __restrict__ B,
    const float* __restrict__ bias, float* __restrict__ C,
    const int* __restrict__ rowmap, int N, int K, int M)
{
    __shared__ float As[16][64];   // [k][row]
    __shared__ float Bs[16][64];   // [k][col]
    const int tid  = threadIdx.x;
    const int tx   = tid & 15;
    const int ty   = tid >> 4;
    const int brow = blockIdx.y << 6;
    const int bcol = blockIdx.x << 6;

    // A tile loader: 64 rows x 16 k, one float4 per thread
    const int a_row = tid >> 2;
    const int a_col = (tid & 3) << 2;
    int a_src = brow + a_row;
    if (GATHER) a_src = rowmap[a_src];
    const float* a_ptr = A + (size_t)a_src * K + a_col;

    // B tile loader
    int b_r, b_c;
    const float* b_ptr;
    if (TRANSB) {
        b_r = tid >> 2;            // m_local 0..63
        b_c = (tid & 3) << 2;      // k offset
        b_ptr = B + (size_t)(bcol + b_r) * K + b_c;
    } else {
        b_r = tid >> 4;            // k 0..15
        b_c = (tid & 15) << 2;     // m offset
        b_ptr = B + (size_t)b_r * M + bcol + b_c;
    }

    float acc[4][4];
#pragma unroll
    for (int i = 0; i < 4; i++)
#pragma unroll
        for (int j = 0; j < 4; j++) acc[i][j] = 0.f;

    for (int k0 = 0; k0 < K; k0 += 16) {
        float4 av = *(const float4*)(a_ptr + k0);
        float4 bv;
        if (TRANSB) bv = *(const float4*)(b_ptr + k0);
        else        bv = *(const float4*)(b_ptr + (size_t)k0 * M);

        As[a_col + 0][a_row] = av.x;
        As[a_col + 1][a_row] = av.y;
        As[a_col + 2][a_row] = av.z;
        As[a_col + 3][a_row] = av.w;
        if (TRANSB) {
            Bs[b_c + 0][b_r] = bv.x;
            Bs[b_c + 1][b_r] = bv.y;
            Bs[b_c + 2][b_r] = bv.z;
            Bs[b_c + 3][b_r] = bv.w;
        } else {
            *(float4*)&Bs[b_r][b_c] = bv;
        }
        __syncthreads();

#pragma unroll
        for (int kk = 0; kk < 16; kk++) {
            float4 a4 = *(const float4*)&As[kk][ty << 2];
            float4 b4 = *(const float4*)&Bs[kk][tx << 2];
            float ar[4] = {a4.x, a4.y, a4.z, a4.w};
            float br[4] = {b4.x, b4.y, b4.z, b4.w};
#pragma unroll
            for (int i = 0; i < 4; i++)
#pragma unroll
                for (int j = 0; j < 4; j++)
                    acc[i][j] = fmaf(ar[i], br[j], acc[i][j]);
        }
        __syncthreads();
    }

    float4 bv4 = make_float4(0.f, 0.f, 0.f, 0.f);
    if (HASBIAS) bv4 = *(const float4*)(bias + bcol + (tx << 2));
#pragma unroll
    for (int i = 0; i < 4; i++) {
        float4 o;
        o.x = acc[i][0] + bv4.x;
        o.y = acc[i][1] + bv4.y;
        o.z = acc[i][2] + bv4.z;
        o.w = acc[i][3] + bv4.w;
        if (RELU) {
            o.x = fmaxf(o.x, 0.f); o.y = fmaxf(o.y, 0.f);
            o.z = fmaxf(o.z, 0.f); o.w = fmaxf(o.w, 0.f);
        }
        *(float4*)(C + (size_t)(brow + (ty << 2) + i) * M + bcol + (tx << 2)) = o;
    }
}

// ---------------- VQ: argmin over 512 codes + commitment partial ----------
// 256 threads = 64 tokens x 4 lanes. dots[t][k] precomputed; d = csq[k]-2*dot.
__global__ void __launch_bounds__(256) vq_kernel(
    const float* __restrict__ dots, const float* __restrict__ z,
    const float* __restrict__ cb, float* __restrict__ out_idx)
{
    __shared__ float s_csq[CBK];
    __shared__ float s_part[8];
    const int tid = threadIdx.x;
    s_csq[tid]       = g_csq[tid];
    s_csq[tid + 256] = g_csq[tid + 256];
    __syncthreads();

    const int token = (blockIdx.x << 6) + (tid >> 2);
    const int part  = tid & 3;
    const int kbase = part << 7;   // 128 codes per lane

    const float4* drow = (const float4*)(dots + (size_t)token * CBK + kbase);
    float best = 3.4e38f;
    int   bidx = kbase;
#pragma unroll 8
    for (int i = 0; i < 32; i++) {
        float4 d4 = drow[i];
        int k = kbase + (i << 2);
        float v;
        v = s_csq[k + 0] - 2.f * d4.x; if (v < best) { best = v; bidx = k + 0; }
        v = s_csq[k + 1] - 2.f * d4.y; if (v < best) { best = v; bidx = k + 1; }
        v = s_csq[k + 2] - 2.f * d4.z; if (v < best) { best = v; bidx = k + 2; }
        v = s_csq[k + 3] - 2.f * d4.w; if (v < best) { best = v; bidx = k + 3; }
    }
    // reduce across the 4 adjacent lanes; ties -> smaller index (jnp.argmin)
#pragma unroll
    for (int off = 1; off < 4; off <<= 1) {
        float ob = __shfl_xor_sync(0xffffffffu, best, off);
        int   oi = __shfl_xor_sync(0xffffffffu, bidx, off);
        if (ob < best || (ob == best && oi < bidx)) { best = ob; bidx = oi; }
    }
    if (part == 0) {
        g_idxbuf[token] = bidx;
        out_idx[token]  = (float)bidx;
    }

    // commitment: sum (z - q)^2 ; each lane handles 64 of 256 coords
    const float4* zr = (const float4*)(z  + (size_t)token * CBD + (part << 6));
    const float4* qr = (const float4*)(cb + (size_t)bidx  * CBD + (part << 6));
    float s = 0.f;
#pragma unroll
    for (int i = 0; i < 16; i++) {
        float4 a = zr[i], b = qr[i];
        float dx = a.x - b.x, dy = a.y - b.y, dz = a.z - b.z, dw = a.w - b.w;
        s += dx*dx + dy*dy + dz*dz + dw*dw;
    }
#pragma unroll
    for (int off = 16; off; off >>= 1) s += __shfl_xor_sync(0xffffffffu, s, off);
    if ((tid & 31) == 0) s_part[tid >> 5] = s;
    __syncthreads();
    if (tid == 0) {
        float t = 0.f;
#pragma unroll
        for (int w = 0; w < 8; w++) t += s_part[w];
        atomicAdd(&g_commit, (double)t);
    }
}

__global__ void finalize_kernel(float* __restrict__ out_loss) {
    *out_loss = (float)(g_commit * (1.0 / ((double)NTOK * CBD)));
}

// ---------------- launch ---------------------------------------------------
extern "C" void kernel_launch(void* const* d_in, const int* in_sizes, int n_in,
                              void* d_out, int out_size) {
    const float* x  = (const float*)d_in[0];
    const float* W1 = (const float*)d_in[1];
    const float* b1 = (const float*)d_in[2];
    const float* W2 = (const float*)d_in[3];
    const float* b2 = (const float*)d_in[4];
    const float* cb = (const float*)d_in[5];
    const float* W3 = (const float*)d_in[6];
    const float* b3 = (const float*)d_in[7];
    const float* W4 = (const float*)d_in[8];
    const float* b4 = (const float*)d_in[9];

    float* out       = (float*)d_out;
    float* out_recon = out;                                // [NTOK*768]
    float* out_idx   = out + (size_t)NTOK * D_IN;          // [NTOK]
    float* out_loss  = out_idx + NTOK;                     // [1]

    float* ph;  float* pz;  int* pidx;
    cudaGetSymbolAddress((void**)&ph,   g_h);
    cudaGetSymbolAddress((void**)&pz,   g_z);
    cudaGetSymbolAddress((void**)&pidx, g_idxbuf);

    // 0) csq + zero commit
    prep_kernel<<<1, CBK>>>(cb);
    // 1) h = relu(x @ W1 + b1)                 [65536,768]x[768,512]
    sgemm_kernel<true , false, false, true ><<<dim3(HID  / 64, NTOK / 64), 256>>>(
        x,  W1, b1, ph, nullptr, NTOK, D_IN, HID);
    // 2) z = h @ W2 + b2                       [65536,512]x[512,256]
    sgemm_kernel<false, false, false, true ><<<dim3(CBD  / 64, NTOK / 64), 256>>>(
        ph, W2, b2, pz, nullptr, NTOK, HID, CBD);
    // 3) dots = z @ cb^T  (into dead h buffer) [65536,256]x[256,512]
    sgemm_kernel<false, false, true , false><<<dim3(CBK  / 64, NTOK / 64), 256>>>(
        pz, cb, nullptr, ph, nullptr, NTOK, CBD, CBK);
    // 4) argmin + indices + commitment partials
    vq_kernel<<<NTOK / 64, 256>>>(ph, pz, cb, out_idx);
    // 5) h2 = relu(codebook[idx] @ W3 + b3)  (gathered A; into dead h buffer)
    sgemm_kernel<true , true , false, true ><<<dim3(HID  / 64, NTOK / 64), 256>>>(
        cb, W3, b3, ph, pidx, NTOK, CBD, HID);
    // 6) recon = h2 @ W4 + b4  -> out
    sgemm_kernel<false, false, false, true ><<<dim3(D_IN / 64, NTOK / 64), 256>>>(
        ph, W4, b4, out_recon, nullptr, NTOK, HID, D_IN);
    // 7) loss -> out
    finalize_kernel<<<1, 1>>>(out_loss);
}

// round 2
// speedup vs baseline: 2.1286x; 2.1286x over previous
#include <cuda_runtime.h>

#define NTOK 65536
#define D_IN 768
#define HID  512
#define CBD  256
#define CBK  512

// ---------------- scratch (device globals; no allocations) ----------------
__device__ float g_h[(size_t)NTOK * HID];   // h, then reused for dots
__device__ float g_z[(size_t)NTOK * CBD];   // z
__device__ float g_T1[512 * 512];           // relu(cb@W3+b3)
__device__ float g_R[512 * 768];            // decoder table
__device__ float g_csq[CBK];
__device__ double g_commit;

// ---------------- prep: codebook norms + zero accumulator -----------------
__global__ void prep_kernel(const float* __restrict__ cb) {
    int k = threadIdx.x;           // 512 threads, one code each
    if (k == 0) g_commit = 0.0;
    const float* row = cb + (size_t)k * CBD;
    float s = 0.f;
#pragma unroll 8
    for (int c = 0; c < CBD; c += 4) {
        float4 v = *(const float4*)(row + c);
        s += v.x*v.x + v.y*v.y + v.z*v.z + v.w*v.w;
    }
    g_csq[k] = s;
}

// ------- tiled SGEMM 128x64, 8x4/thread, reg-prefetch double buffer -------
// C[N,M] = op(A[N,K] @ B + bias). TRANSB: B physical [M,K].
template<bool RELU, bool TRANSB, bool HASBIAS>
__global__ void __launch_bounds__(256) sgemm_kernel(
    const float* __restrict__ A, const float* __restrict__ B,
    const float* __restrict__ bias, float* __restrict__ C,
    int N, int K, int M)
{
    __shared__ float As[16][132];   // [k][row], padded (2-way store conflicts ok)
    __shared__ float Bs[16][72];    // [k][col], padded, float4-aligned stride

    const int tid  = threadIdx.x;
    const int tx   = tid & 15;          // col group (4 cols)
    const int ty   = tid >> 4;          // row group (8 rows)
    const int brow = blockIdx.y << 7;   // 128 rows
    const int bcol = blockIdx.x << 6;   // 64 cols

    // A loader: two rows per thread (r, r+64), 4 consecutive k
    const int ar = tid >> 2;
    const int ac = (tid & 3) << 2;
    const float* a0 = A + (size_t)(brow + ar) * K + ac;
    const float* a1 = A + (size_t)(brow + ar + 64) * K + ac;

    // B loader
    int br, bc;
    const float* bptr;
    if (TRANSB) {
        br = tid >> 2;                  // col 0..63
        bc = (tid & 3) << 2;            // k offset
        bptr = B + (size_t)(bcol + br) * K + bc;
    } else {
        br = tid >> 4;                  // k 0..15
        bc = (tid & 15) << 2;           // col offset
        bptr = B + (size_t)br * M + bcol + bc;
    }

    float acc[8][4];
#pragma unroll
    for (int i = 0; i < 8; i++)
#pragma unroll
        for (int j = 0; j < 4; j++) acc[i][j] = 0.f;

    float4 av0 = *(const float4*)a0;
    float4 av1 = *(const float4*)a1;
    float4 bv;
    if (TRANSB) bv = *(const float4*)bptr;
    else        bv = *(const float4*)bptr;

    for (int k0 = 0; k0 < K; k0 += 16) {
        // stage current tile to smem
        As[ac + 0][ar] = av0.x;  As[ac + 1][ar] = av0.y;
        As[ac + 2][ar] = av0.z;  As[ac + 3][ar] = av0.w;
        As[ac + 0][ar + 64] = av1.x;  As[ac + 1][ar + 64] = av1.y;
        As[ac + 2][ar + 64] = av1.z;  As[ac + 3][ar + 64] = av1.w;
        if (TRANSB) {
            Bs[bc + 0][br] = bv.x;  Bs[bc + 1][br] = bv.y;
            Bs[bc + 2][br] = bv.z;  Bs[bc + 3][br] = bv.w;
        } else {
            *(float4*)&Bs[br][bc] = bv;
        }
        __syncthreads();

        // prefetch next tile into registers
        if (k0 + 16 < K) {
            av0 = *(const float4*)(a0 + k0 + 16);
            av1 = *(const float4*)(a1 + k0 + 16);
            if (TRANSB) bv = *(const float4*)(bptr + k0 + 16);
            else        bv = *(const float4*)(bptr + (size_t)(k0 + 16) * M);
        }

        // compute
#pragma unroll
        for (int kk = 0; kk < 16; kk++) {
            float4 a4l = *(const float4*)&As[kk][ty << 3];
            float4 a4h = *(const float4*)&As[kk][(ty << 3) + 4];
            float4 b4  = *(const float4*)&Bs[kk][tx << 2];
            float arr[8] = {a4l.x, a4l.y, a4l.z, a4l.w,
                            a4h.x, a4h.y, a4h.z, a4h.w};
            float brr[4] = {b4.x, b4.y, b4.z, b4.w};
#pragma unroll
            for (int i = 0; i < 8; i++)
#pragma unroll
                for (int j = 0; j < 4; j++)
                    acc[i][j] = fmaf(arr[i], brr[j], acc[i][j]);
        }
        __syncthreads();
    }

    float4 bb = make_float4(0.f, 0.f, 0.f, 0.f);
    if (HASBIAS) bb = *(const float4*)(bias + bcol + (tx << 2));
#pragma unroll
    for (int i = 0; i < 8; i++) {
        float4 o;
        o.x = acc[i][0] + bb.x;
        o.y = acc[i][1] + bb.y;
        o.z = acc[i][2] + bb.z;
        o.w = acc[i][3] + bb.w;
        if (RELU) {
            o.x = fmaxf(o.x, 0.f); o.y = fmaxf(o.y, 0.f);
            o.z = fmaxf(o.z, 0.f); o.w = fmaxf(o.w, 0.f);
        }
        *(float4*)(C + (size_t)(brow + (ty << 3) + i) * M + bcol + (tx << 2)) = o;
    }
}

// ---- VQ: argmin + commit partial + recon gather from decoder table -------
// 256 threads = 64 tokens x 4 lanes.
__global__ void __launch_bounds__(256) vq_recon_kernel(
    const float* __restrict__ dots, const float* __restrict__ z,
    const float* __restrict__ R, float* __restrict__ out_idx,
    float* __restrict__ out_recon)
{
    __shared__ float s_csq[CBK];
    __shared__ float s_part[8];
    const int tid = threadIdx.x;
    s_csq[tid]       = g_csq[tid];
    s_csq[tid + 256] = g_csq[tid + 256];
    __syncthreads();

    const int token = (blockIdx.x << 6) + (tid >> 2);
    const int part  = tid & 3;
    const int kbase = part << 7;   // 128 codes per lane

    const float4* drow = (const float4*)(dots + (size_t)token * CBK + kbase);
    float best = 3.4e38f;
    int   bidx = kbase;
#pragma unroll 8
    for (int i = 0; i < 32; i++) {
        float4 d4 = drow[i];
        int k = kbase + (i << 2);
        float v;
        v = s_csq[k + 0] - 2.f * d4.x; if (v < best) { best = v; bidx = k + 0; }
        v = s_csq[k + 1] - 2.f * d4.y; if (v < best) { best = v; bidx = k + 1; }
        v = s_csq[k + 2] - 2.f * d4.z; if (v < best) { best = v; bidx = k + 2; }
        v = s_csq[k + 3] - 2.f * d4.w; if (v < best) { best = v; bidx = k + 3; }
    }
    // reduce across the 4 lanes of this token; ties -> smaller index
#pragma unroll
    for (int off = 1; off < 4; off <<= 1) {
        float ob = __shfl_xor_sync(0xffffffffu, best, off);
        int   oi = __shfl_xor_sync(0xffffffffu, bidx, off);
        if (ob < best || (ob == best && oi < bidx)) { best = ob; bidx = oi; }
    }

    // ||z||^2 over this lane's 64 coords, reduced across 4 lanes
    const float4* zr = (const float4*)(z + (size_t)token * CBD + (part << 6));
    float s = 0.f;
#pragma unroll
    for (int i = 0; i < 16; i++) {
        float4 a = zr[i];
        s += a.x*a.x + a.y*a.y + a.z*a.z + a.w*a.w;
    }
    s += __shfl_xor_sync(0xffffffffu, s, 1);
    s += __shfl_xor_sync(0xffffffffu, s, 2);

    // commit_t = ||z||^2 - 2 z.q + ||q||^2 = zsq + best
    float cv = (part == 0) ? (s + best) : 0.f;
    if (part == 0) out_idx[token] = (float)bidx;

    // recon[t] = R[bidx] (each lane copies 192 of 768 floats)
    const float4* src = (const float4*)(R + (size_t)bidx * D_IN + part * 192);
    float4*       dst = (float4*)(out_recon + (size_t)token * D_IN + part * 192);
#pragma unroll 4
    for (int i = 0; i < 48; i++) dst[i] = src[i];

    // block-level commit reduction
#pragma unroll
    for (int off = 16; off; off >>= 1) cv += __shfl_xor_sync(0xffffffffu, cv, off);
    if ((tid & 31) == 0) s_part[tid >> 5] = cv;
    __syncthreads();
    if (tid == 0) {
        float t = 0.f;
#pragma unroll
        for (int w = 0; w < 8; w++) t += s_part[w];
        atomicAdd(&g_commit, (double)t);
    }
}

__global__ void finalize_kernel(float* __restrict__ out_loss) {
    *out_loss = (float)(g_commit * (1.0 / ((double)NTOK * CBD)));
}

// ---------------- launch ---------------------------------------------------
extern "C" void kernel_launch(void* const* d_in, const int* in_sizes, int n_in,
                              void* d_out, int out_size) {
    const float* x  = (const float*)d_in[0];
    const float* W1 = (const float*)d_in[1];
    const float* b1 = (const float*)d_in[2];
    const float* W2 = (const float*)d_in[3];
    const float* b2 = (const float*)d_in[4];
    const float* cb = (const float*)d_in[5];
    const float* W3 = (const float*)d_in[6];
    const float* b3 = (const float*)d_in[7];
    const float* W4 = (const float*)d_in[8];
    const float* b4 = (const float*)d_in[9];

    float* out       = (float*)d_out;
    float* out_recon = out;                                // [NTOK*768]
    float* out_idx   = out + (size_t)NTOK * D_IN;          // [NTOK]
    float* out_loss  = out_idx + NTOK;                     // [1]

    float* ph; float* pz; float* pT1; float* pR;
    cudaGetSymbolAddress((void**)&ph,  g_h);
    cudaGetSymbolAddress((void**)&pz,  g_z);
    cudaGetSymbolAddress((void**)&pT1, g_T1);
    cudaGetSymbolAddress((void**)&pR,  g_R);

    // 0) csq + zero commit
    prep_kernel<<<1, CBK>>>(cb);
    // decoder table (tiny): T1 = relu(cb@W3+b3) [512,512]; R = T1@W4+b4 [512,768]
    sgemm_kernel<true , false, true ><<<dim3(HID  / 64, 512 / 128), 256>>>(
        cb,  W3, b3, pT1, 512, CBD, HID);
    sgemm_kernel<false, false, true ><<<dim3(D_IN / 64, 512 / 128), 256>>>(
        pT1, W4, b4, pR,  512, HID, D_IN);
    // 1) h = relu(x @ W1 + b1)                 [65536,768]x[768,512]
    sgemm_kernel<true , false, true ><<<dim3(HID  / 64, NTOK / 128), 256>>>(
        x,  W1, b1, ph, NTOK, D_IN, HID);
    // 2) z = h @ W2 + b2                       [65536,512]x[512,256]
    sgemm_kernel<false, false, true ><<<dim3(CBD  / 64, NTOK / 128), 256>>>(
        ph, W2, b2, pz, NTOK, HID, CBD);
    // 3) dots = z @ cb^T (into dead h buffer)  [65536,256]x[256,512]
    sgemm_kernel<false, true , false><<<dim3(CBK  / 64, NTOK / 128), 256>>>(
        pz, cb, nullptr, ph, NTOK, CBD, CBK);
    // 4) argmin + indices + commit + recon gather
    vq_recon_kernel<<<NTOK / 64, 256>>>(ph, pz, pR, out_idx, out_recon);
    // 5) loss -> out
    finalize_kernel<<<1, 1>>>(out_loss);
}

// round 5
// speedup vs baseline: 2.1915x; 1.0296x over previous
#include <cuda_runtime.h>
#include <cstdint>

#define NTOK 65536
#define D_IN 768
#define HID  512
#define CBD  256
#define CBK  512

// ---------------- scratch (device globals; no allocations) ----------------
__device__ float g_h[(size_t)NTOK * HID];   // h, then reused for dots
__device__ float g_z[(size_t)NTOK * CBD];   // z
__device__ float g_T1[512 * 512];           // relu(cb@W3+b3)
__device__ float g_R[512 * 768];            // decoder table
__device__ float g_W1T[HID * D_IN];         // W1 transposed [512,768]
__device__ float g_W2T[CBD * HID];          // W2 transposed [256,512]
__device__ float g_csq[CBK];
__device__ double g_commit;

// ---------------- helpers --------------------------------------------------
__device__ __forceinline__ uint32_t f32_tf32(float f) {
    uint32_t r; asm("cvt.rna.tf32.f32 %0, %1;" : "=r"(r) : "f"(f)); return r;
}
__device__ __forceinline__ void split4(float4 v, uint4& h, uint4& l) {
    h.x = f32_tf32(v.x); l.x = f32_tf32(v.x - __uint_as_float(h.x));
    h.y = f32_tf32(v.y); l.y = f32_tf32(v.y - __uint_as_float(h.y));
    h.z = f32_tf32(v.z); l.z = f32_tf32(v.z - __uint_as_float(h.z));
    h.w = f32_tf32(v.w); l.w = f32_tf32(v.w - __uint_as_float(h.w));
}
#define MMA_TF32(cc, aa, bb) \
    asm volatile("mma.sync.aligned.m16n8k8.row.col.f32.tf32.tf32.f32 " \
        "{%0,%1,%2,%3}, {%4,%5,%6,%7}, {%8,%9}, {%0,%1,%2,%3};" \
        : "+f"((cc)[0]), "+f"((cc)[1]), "+f"((cc)[2]), "+f"((cc)[3]) \
        : "r"((aa)[0]), "r"((aa)[1]), "r"((aa)[2]), "r"((aa)[3]), \
          "r"((bb)[0]), "r"((bb)[1]))

// =================== mma.sync tf32 3x-split GEMM ===========================
// C[N, M] = op(A[N, K] @ Bt^T + bias), Bt is [M, K] fp32 row-major.
// CTA tile 128x128, 8 warps each 64x32 (4x4 m16n8k8 frags), K-tile 16.
// smem: hi/lo tf32 tiles, [row][k] stride 20 words (conflict-free frag loads).
template<bool RELU, bool HASBIAS>
__global__ void __launch_bounds__(256) mma_gemm(
    const float* __restrict__ A, const float* __restrict__ Bt,
    const float* __restrict__ bias, float* __restrict__ C, int K, int M)
{
    __shared__ uint32_t AsH[128][20];
    __shared__ uint32_t AsL[128][20];
    __shared__ uint32_t BsH[128][20];
    __shared__ uint32_t BsL[128][20];

    const int tid   = threadIdx.x;
    const int lane  = tid & 31;
    const int wid   = tid >> 5;
    const int wm    = wid & 1;          // m band (2 x 64)
    const int wn    = wid >> 1;         // n band (4 x 32)
    const int group = lane >> 2;
    const int tig   = lane & 3;
    const int brow  = blockIdx.y << 7;
    const int bcol  = blockIdx.x << 7;

    // loader: each thread owns 2 rows (r0, r0+64), 4 consecutive k
    const int r0 = tid >> 2;
    const int kc = (tid & 3) << 2;
    const float* aP0 = A  + (size_t)(brow + r0)      * K + kc;
    const float* aP1 = A  + (size_t)(brow + r0 + 64) * K + kc;
    const float* bP0 = Bt + (size_t)(bcol + r0)      * K + kc;
    const float* bP1 = Bt + (size_t)(bcol + r0 + 64) * K + kc;

    float c[4][4][4];
#pragma unroll
    for (int i = 0; i < 4; i++)
#pragma unroll
        for (int j = 0; j < 4; j++)
#pragma unroll
            for (int k = 0; k < 4; k++) c[i][j][k] = 0.f;

    float4 va0 = *(const float4*)aP0;
    float4 va1 = *(const float4*)aP1;
    float4 vb0 = *(const float4*)bP0;
    float4 vb1 = *(const float4*)bP1;

    const int KT = K >> 4;
    for (int kt = 0; kt < KT; kt++) {
        // convert + stage to smem
        uint4 h, l;
        split4(va0, h, l);
        *(uint4*)&AsH[r0][kc] = h;       *(uint4*)&AsL[r0][kc] = l;
        split4(va1, h, l);
        *(uint4*)&AsH[r0 + 64][kc] = h;  *(uint4*)&AsL[r0 + 64][kc] = l;
        split4(vb0, h, l);
        *(uint4*)&BsH[r0][kc] = h;       *(uint4*)&BsL[r0][kc] = l;
        split4(vb1, h, l);
        *(uint4*)&BsH[r0 + 64][kc] = h;  *(uint4*)&BsL[r0 + 64][kc] = l;
        __syncthreads();

        // prefetch next K-tile into registers
        if (kt + 1 < KT) {
            const int ko = (kt + 1) << 4;
            va0 = *(const float4*)(aP0 + ko);
            va1 = *(const float4*)(aP1 + ko);
            vb0 = *(const float4*)(bP0 + ko);
            vb1 = *(const float4*)(bP1 + ko);
        }

        // compute: 2 k8 steps
#pragma unroll
        for (int ks = 0; ks < 2; ks++) {
            const int k0 = ks << 3;
            uint32_t ah[4][4], al[4][4];
#pragma unroll
            for (int mf = 0; mf < 4; mf++) {
                const int row = (wm << 6) + (mf << 4) + group;
                ah[mf][0] = AsH[row][k0 + tig];
                ah[mf][1] = AsH[row + 8][k0 + tig];
                ah[mf][2] = AsH[row][k0 + tig + 4];
                ah[mf][3] = AsH[row + 8][k0 + tig + 4];
                al[mf][0] = AsL[row][k0 + tig];
                al[mf][1] = AsL[row + 8][k0 + tig];
                al[mf][2] = AsL[row][k0 + tig + 4];
                al[mf][3] = AsL[row + 8][k0 + tig + 4];
            }
            uint32_t bh[4][2], bl[4][2];
#pragma unroll
            for (int nf = 0; nf < 4; nf++) {
                const int col = (wn << 5) + (nf << 3) + group;
                bh[nf][0] = BsH[col][k0 + tig];
                bh[nf][1] = BsH[col][k0 + tig + 4];
                bl[nf][0] = BsL[col][k0 + tig];
                bl[nf][1] = BsL[col][k0 + tig + 4];
            }
#pragma unroll
            for (int mf = 0; mf < 4; mf++)
#pragma unroll
                for (int nf = 0; nf < 4; nf++) {
                    MMA_TF32(c[mf][nf], ah[mf], bh[nf]);
                    MMA_TF32(c[mf][nf], al[mf], bh[nf]);
                    MMA_TF32(c[mf][nf], ah[mf], bl[nf]);
                }
        }
        __syncthreads();
    }

    // epilogue
#pragma unroll
    for (int mf = 0; mf < 4; mf++) {
#pragma unroll
        for (int nf = 0; nf < 4; nf++) {
            const int row = brow + (wm << 6) + (mf << 4) + group;
            const int col = bcol + (wn << 5) + (nf << 3) + (tig << 1);
            float bx = 0.f, by = 0.f;
            if (HASBIAS) { bx = __ldg(bias + col); by = __ldg(bias + col + 1); }
            float2 o0, o1;
            o0.x = c[mf][nf][0] + bx;  o0.y = c[mf][nf][1] + by;
            o1.x = c[mf][nf][2] + bx;  o1.y = c[mf][nf][3] + by;
            if (RELU) {
                o0.x = fmaxf(o0.x, 0.f); o0.y = fmaxf(o0.y, 0.f);
                o1.x = fmaxf(o1.x, 0.f); o1.y = fmaxf(o1.y, 0.f);
            }
            *(float2*)(C + (size_t)row * M + col)       = o0;
            *(float2*)(C + (size_t)(row + 8) * M + col) = o1;
        }
    }
}

// ---------------- prep kernels ---------------------------------------------
__global__ void prep_kernel(const float* __restrict__ cb) {
    int k = threadIdx.x;
    if (k == 0) g_commit = 0.0;
    const float* row = cb + (size_t)k * CBD;
    float s = 0.f;
#pragma unroll 8
    for (int c = 0; c < CBD; c += 4) {
        float4 v = *(const float4*)(row + c);
        s += v.x*v.x + v.y*v.y + v.z*v.z + v.w*v.w;
    }
    g_csq[k] = s;
}

__global__ void transpose_kernel(const float* __restrict__ W, float* __restrict__ WT,
                                 int K, int M) {
    int idx = blockIdx.x * 256 + threadIdx.x;
    if (idx < K * M) {
        int m = idx / K, k = idx - m * K;
        WT[idx] = W[(size_t)k * M + m];
    }
}

// ---------------- fp32 SGEMM for the tiny decoder-table GEMMs -------------
template<bool RELU, bool HASBIAS>
__global__ void __launch_bounds__(256) sgemm_kernel(
    const float* __restrict__ A, const float* __restrict__ B,
    const float* __restrict__ bias, float* __restrict__ C,
    int N, int K, int M)
{
    __shared__ float As[16][132];
    __shared__ float Bs[16][72];
    const int tid  = threadIdx.x;
    const int tx   = tid & 15;
    const int ty   = tid >> 4;
    const int brow = blockIdx.y << 7;
    const int bcol = blockIdx.x << 6;

    const int ar = tid >> 2;
    const int ac = (tid & 3) << 2;
    const float* a0 = A + (size_t)(brow + ar) * K + ac;
    const float* a1 = A + (size_t)(brow + ar + 64) * K + ac;
    const int br = tid >> 4;
    const int bc = (tid & 15) << 2;
    const float* bptr = B + (size_t)br * M + bcol + bc;

    float acc[8][4];
#pragma unroll
    for (int i = 0; i < 8; i++)
#pragma unroll
        for (int j = 0; j < 4; j++) acc[i][j] = 0.f;

    for (int k0 = 0; k0 < K; k0 += 16) {
        float4 av0 = *(const float4*)(a0 + k0);
        float4 av1 = *(const float4*)(a1 + k0);
        float4 bv  = *(const float4*)(bptr + (size_t)k0 * M);
        As[ac + 0][ar] = av0.x;  As[ac + 1][ar] = av0.y;
        As[ac + 2][ar] = av0.z;  As[ac + 3][ar] = av0.w;
        As[ac + 0][ar + 64] = av1.x;  As[ac + 1][ar + 64] = av1.y;
        As[ac + 2][ar + 64] = av1.z;  As[ac + 3][ar + 64] = av1.w;
        *(float4*)&Bs[br][bc] = bv;
        __syncthreads();
#pragma unroll
        for (int kk = 0; kk < 16; kk++) {
            float4 a4l = *(const float4*)&As[kk][ty << 3];
            float4 a4h = *(const float4*)&As[kk][(ty << 3) + 4];
            float4 b4  = *(const float4*)&Bs[kk][tx << 2];
            float arr[8] = {a4l.x, a4l.y, a4l.z, a4l.w, a4h.x, a4h.y, a4h.z, a4h.w};
            float brr[4] = {b4.x, b4.y, b4.z, b4.w};
#pragma unroll
            for (int i = 0; i < 8; i++)
#pragma unroll
                for (int j = 0; j < 4; j++)
                    acc[i][j] = fmaf(arr[i], brr[j], acc[i][j]);
        }
        __syncthreads();
    }

    float4 bb = make_float4(0.f, 0.f, 0.f, 0.f);
    if (HASBIAS) bb = *(const float4*)(bias + bcol + (tx << 2));
#pragma unroll
    for (int i = 0; i < 8; i++) {
        float4 o;
        o.x = acc[i][0] + bb.x;
        o.y = acc[i][1] + bb.y;
        o.z = acc[i][2] + bb.z;
        o.w = acc[i][3] + bb.w;
        if (RELU) {
            o.x = fmaxf(o.x, 0.f); o.y = fmaxf(o.y, 0.f);
            o.z = fmaxf(o.z, 0.f); o.w = fmaxf(o.w, 0.f);
        }
        *(float4*)(C + (size_t)(brow + (ty << 3) + i) * M + bcol + (tx << 2)) = o;
    }
}

// ---- VQ: argmin + commit partial + recon gather from decoder table -------
__global__ void __launch_bounds__(256) vq_recon_kernel(
    const float* __restrict__ dots, const float* __restrict__ z,
    const float* __restrict__ R, float* __restrict__ out_idx,
    float* __restrict__ out_recon)
{
    __shared__ float s_csq[CBK];
    __shared__ float s_part[8];
    const int tid = threadIdx.x;
    s_csq[tid]       = g_csq[tid];
    s_csq[tid + 256] = g_csq[tid + 256];
    __syncthreads();

    const int token = (blockIdx.x << 6) + (tid >> 2);
    const int part  = tid & 3;
    const int kbase = part << 7;

    const float4* drow = (const float4*)(dots + (size_t)token * CBK + kbase);
    float best = 3.4e38f;
    int   bidx = kbase;
#pragma unroll 8
    for (int i = 0; i < 32; i++) {
        float4 d4 = drow[i];
        int k = kbase + (i << 2);
        float v;
        v = s_csq[k + 0] - 2.f * d4.x; if (v < best) { best = v; bidx = k + 0; }
        v = s_csq[k + 1] - 2.f * d4.y; if (v < best) { best = v; bidx = k + 1; }
        v = s_csq[k + 2] - 2.f * d4.z; if (v < best) { best = v; bidx = k + 2; }
        v = s_csq[k + 3] - 2.f * d4.w; if (v < best) { best = v; bidx = k + 3; }
    }
#pragma unroll
    for (int off = 1; off < 4; off <<= 1) {
        float ob = __shfl_xor_sync(0xffffffffu, best, off);
        int   oi = __shfl_xor_sync(0xffffffffu, bidx, off);
        if (ob < best || (ob == best && oi < bidx)) { best = ob; bidx = oi; }
    }

    const float4* zr = (const float4*)(z + (size_t)token * CBD + (part << 6));
    float s = 0.f;
#pragma unroll
    for (int i = 0; i < 16; i++) {
        float4 a = zr[i];
        s += a.x*a.x + a.y*a.y + a.z*a.z + a.w*a.w;
    }
    s += __shfl_xor_sync(0xffffffffu, s, 1);
    s += __shfl_xor_sync(0xffffffffu, s, 2);

    float cv = (part == 0) ? (s + best) : 0.f;
    if (part == 0) out_idx[token] = (float)bidx;

    const float4* src = (const float4*)(R + (size_t)bidx * D_IN + part * 192);
    float4*       dst = (float4*)(out_recon + (size_t)token * D_IN + part * 192);
#pragma unroll 4
    for (int i = 0; i < 48; i++) dst[i] = src[i];

#pragma unroll
    for (int off = 16; off; off >>= 1) cv += __shfl_xor_sync(0xffffffffu, cv, off);
    if ((tid & 31) == 0) s_part[tid >> 5] = cv;
    __syncthreads();
    if (tid == 0) {
        float t = 0.f;
#pragma unroll
        for (int w = 0; w < 8; w++) t += s_part[w];
        atomicAdd(&g_commit, (double)t);
    }
}

__global__ void finalize_kernel(float* __restrict__ out_loss) {
    *out_loss = (float)(g_commit * (1.0 / ((double)NTOK * CBD)));
}

// ---------------- launch ---------------------------------------------------
extern "C" void kernel_launch(void* const* d_in, const int* in_sizes, int n_in,
                              void* d_out, int out_size) {
    const float* x  = (const float*)d_in[0];
    const float* W1 = (const float*)d_in[1];
    const float* b1 = (const float*)d_in[2];
    const float* W2 = (const float*)d_in[3];
    const float* b2 = (const float*)d_in[4];
    const float* cb = (const float*)d_in[5];
    const float* W3 = (const float*)d_in[6];
    const float* b3 = (const float*)d_in[7];
    const float* W4 = (const float*)d_in[8];
    const float* b4 = (const float*)d_in[9];

    float* out       = (float*)d_out;
    float* out_recon = out;
    float* out_idx   = out + (size_t)NTOK * D_IN;
    float* out_loss  = out_idx + NTOK;

    float *ph, *pz, *pT1, *pR, *pW1T, *pW2T;
    cudaGetSymbolAddress((void**)&ph,   g_h);
    cudaGetSymbolAddress((void**)&pz,   g_z);
    cudaGetSymbolAddress((void**)&pT1,  g_T1);
    cudaGetSymbolAddress((void**)&pR,   g_R);
    cudaGetSymbolAddress((void**)&pW1T, g_W1T);
    cudaGetSymbolAddress((void**)&pW2T, g_W2T);

    // prep: csq, commit=0, weight transposes
    prep_kernel<<<1, CBK>>>(cb);
    transpose_kernel<<<(HID * D_IN + 255) / 256, 256>>>(W1, pW1T, D_IN, HID);
    transpose_kernel<<<(CBD * HID + 255) / 256, 256>>>(W2, pW2T, HID, CBD);

    // decoder table (tiny, fp32): T1 = relu(cb@W3+b3); R = T1@W4+b4
    sgemm_kernel<true , true ><<<dim3(HID  / 64, 512 / 128), 256>>>(cb,  W3, b3, pT1, 512, CBD, HID);
    sgemm_kernel<false, true ><<<dim3(D_IN / 64, 512 / 128), 256>>>(pT1, W4, b4, pR,  512, HID, D_IN);

    // 1) h = relu(x @ W1 + b1)          [65536,768] x W1T[512,768]
    mma_gemm<true,  true ><<<dim3(HID / 128, NTOK / 128), 256>>>(x,  pW1T, b1, ph, D_IN, HID);
    // 2) z = h @ W2 + b2                [65536,512] x W2T[256,512]
    mma_gemm<false, true ><<<dim3(CBD / 128, NTOK / 128), 256>>>(ph, pW2T, b2, pz, HID, CBD);
    // 3) dots = z @ cb^T                [65536,256] x cb[512,256]
    mma_gemm<false, false><<<dim3(CBK / 128, NTOK / 128), 256>>>(pz, cb, nullptr, ph, CBD, CBK);
    // 4) argmin + indices + commit + recon gather
    vq_recon_kernel<<<NTOK / 64, 256>>>(ph, pz, pR, out_idx, out_recon);
    // 5) loss
    finalize_kernel<<<1, 1>>>(out_loss);
}

// round 6
// speedup vs baseline: 2.3707x; 1.0817x over previous
#include <cuda_runtime.h>
#include <cstdint>

#define NTOK 65536
#define D_IN 768
#define HID  512
#define CBD  256
#define CBK  512

// ---------------- scratch (device globals; no allocations) ----------------
__device__ float g_hH[(size_t)NTOK * HID];
__device__ float g_hL[(size_t)NTOK * HID];
__device__ float g_zH[(size_t)NTOK * CBD];
__device__ float g_zL[(size_t)NTOK * CBD];
__device__ float g_dots[(size_t)NTOK * CBK];
__device__ float g_W1TH[HID * D_IN];
__device__ float g_W1TL[HID * D_IN];
__device__ float g_W2TH[CBD * HID];
__device__ float g_W2TL[CBD * HID];
__device__ float g_cbH[CBK * CBD];
__device__ float g_cbL[CBK * CBD];
__device__ float g_T1[512 * 512];
__device__ float g_R[512 * 768];
__device__ float g_csq[CBK];
__device__ double g_commit;

// ---------------- helpers --------------------------------------------------
__device__ __forceinline__ uint32_t f32_tf32(float f) {
    uint32_t r; asm("cvt.rna.tf32.f32 %0, %1;" : "=r"(r) : "f"(f)); return r;
}
__device__ __forceinline__ float tf32f(float v) { return __uint_as_float(f32_tf32(v)); }
__device__ __forceinline__ void split4(float4 v, uint4& h, uint4& l) {
    h.x = f32_tf32(v.x); l.x = f32_tf32(v.x - __uint_as_float(h.x));
    h.y = f32_tf32(v.y); l.y = f32_tf32(v.y - __uint_as_float(h.y));
    h.z = f32_tf32(v.z); l.z = f32_tf32(v.z - __uint_as_float(h.z));
    h.w = f32_tf32(v.w); l.w = f32_tf32(v.w - __uint_as_float(h.w));
}
__device__ __forceinline__ void cp16(uint32_t saddr, const void* g) {
    asm volatile("cp.async.cg.shared.global [%0], [%1], 16;" :: "r"(saddr), "l"(g));
}
#define CP_COMMIT() asm volatile("cp.async.commit_group;" ::: "memory")
#define CP_WAIT1()  asm volatile("cp.async.wait_group 1;" ::: "memory")

#define MMA_TF32(cc, aa, bb) \
    asm volatile("mma.sync.aligned.m16n8k8.row.col.f32.tf32.tf32.f32 " \
        "{%0,%1,%2,%3}, {%4,%5,%6,%7}, {%8,%9}, {%0,%1,%2,%3};" \
        : "+f"((cc)[0]), "+f"((cc)[1]), "+f"((cc)[2]), "+f"((cc)[3]) \
        : "r"((aa)[0]), "r"((aa)[1]), "r"((aa)[2]), "r"((aa)[3]), \
          "r"((bb)[0]), "r"((bb)[1]))

// =================== mma.sync tf32 3x-split GEMM ===========================
// C[N, M] = op(A[N, K] @ Bt^T + bias). B pre-split (Bh/Bl, [M,K] row-major).
// ASPLIT: A pre-split planes (Ah/Al); else Ah is fp32, converted in-kernel.
// OSPLIT: write hi plane to C, lo plane to Cl.
// CTA tile 128x128, 8 warps each 64x32, K-tile 16, 2-stage smem double buffer.
// stage layout (words): AH 0, AL 2560, BH 5120, BL 7680; stride 20 words/row.
template<bool RELU, bool HASBIAS, bool ASPLIT, bool OSPLIT>
__global__ void __launch_bounds__(256, 2) mma_gemm(
    const float* __restrict__ Ah, const float* __restrict__ Al,
    const float* __restrict__ Bh, const float* __restrict__ Bl,
    const float* __restrict__ bias, float* __restrict__ C,
    float* __restrict__ Cl, int K, int M)
{
    extern __shared__ uint32_t dsm[];   // 2 stages x 10240 words = 81920 B

    const int tid   = threadIdx.x;
    const int lane  = tid & 31;
    const int wid   = tid >> 5;
    const int wm    = wid & 1;
    const int wn    = wid >> 1;
    const int group = lane >> 2;
    const int tig   = lane & 3;
    const int brow  = blockIdx.y << 7;
    const int bcol  = blockIdx.x << 7;

    // loader mapping: 2 rows per thread (r0, r0+64), 4 consecutive k
    const int r0  = tid >> 2;
    const int kc4 = (tid & 3) << 2;

    uint32_t smem0;
    asm("{ .reg .u64 t; cvta.to.shared.u64 t, %1; cvt.u32.u64 %0, t; }"
        : "=r"(smem0) : "l"(dsm));
    const uint32_t ldoff = smem0 + (uint32_t)(r0 * 20 + kc4) * 4;  // byte addr

    const float* aH0 = Ah + (size_t)(brow + r0) * K + kc4;
    const float* aH1 = aH0 + (size_t)64 * K;
    const float* aL0 = ASPLIT ? (Al + (size_t)(brow + r0) * K + kc4) : nullptr;
    const float* aL1 = ASPLIT ? (aL0 + (size_t)64 * K) : nullptr;
    const float* bH0 = Bh + (size_t)(bcol + r0) * K + kc4;
    const float* bH1 = bH0 + (size_t)64 * K;
    const float* bL0 = Bl + (size_t)(bcol + r0) * K + kc4;
    const float* bL1 = bL0 + (size_t)64 * K;

    float c[4][4][4];
#pragma unroll
    for (int i = 0; i < 4; i++)
#pragma unroll
        for (int j = 0; j < 4; j++)
#pragma unroll
            for (int k = 0; k < 4; k++) c[i][j][k] = 0.f;

    const int KT = K >> 4;

    // issue async loads for tile kt into stage (kt&1). B always; A if ASPLIT.
    auto issue = [&](int kt) {
        const uint32_t sb = ldoff + (uint32_t)(kt & 1) * 40960;
        const size_t go = (size_t)kt << 4;
        cp16(sb + 20480,        bH0 + go);
        cp16(sb + 20480 + 5120, bH1 + go);
        cp16(sb + 30720,        bL0 + go);
        cp16(sb + 30720 + 5120, bL1 + go);
        if (ASPLIT) {
            cp16(sb,                aH0 + go);
            cp16(sb + 5120,         aH1 + go);
            cp16(sb + 10240,        aL0 + go);
            cp16(sb + 10240 + 5120, aL1 + go);
        }
    };

    float4 va0, va1;
    if (!ASPLIT) { va0 = *(const float4*)aH0; va1 = *(const float4*)aH1; }
    issue(0); CP_COMMIT();
    issue(1); CP_COMMIT();

    for (int kt = 0; kt < KT; kt++) {
        const uint32_t sw = (uint32_t)(kt & 1) * 10240;   // word base of stage

        if (!ASPLIT) {
            // stage A(kt) via registers (loaded previous iter), convert, STS
            uint4 h, l;
            uint32_t* p0 = dsm + sw + r0 * 20 + kc4;
            split4(va0, h, l);
            *(uint4*)p0 = h;  *(uint4*)(p0 + 2560) = l;
            split4(va1, h, l);
            *(uint4*)(p0 + 64 * 20) = h;  *(uint4*)(p0 + 2560 + 64 * 20) = l;
            if (kt + 1 < KT) {
                const size_t go = (size_t)(kt + 1) << 4;
                va0 = *(const float4*)(aH0 + go);
                va1 = *(const float4*)(aH1 + go);
            }
        }

        CP_WAIT1();
        __syncthreads();

        const uint32_t* sA = dsm + sw;
        const uint32_t* sB = sA + 5120;
#pragma unroll
        for (int ks = 0; ks < 2; ks++) {
            const int k0 = ks << 3;
            uint32_t bh[4][2], bl[4][2];
#pragma unroll
            for (int nf = 0; nf < 4; nf++) {
                const int col = (wn << 5) + (nf << 3) + group;
                bh[nf][0] = sB[col * 20 + k0 + tig];
                bh[nf][1] = sB[col * 20 + k0 + tig + 4];
                bl[nf][0] = sB[2560 + col * 20 + k0 + tig];
                bl[nf][1] = sB[2560 + col * 20 + k0 + tig + 4];
            }
#pragma unroll
            for (int mf = 0; mf < 4; mf++) {
                const int row = (wm << 6) + (mf << 4) + group;
                uint32_t ah[4], al[4];
                ah[0] = sA[row * 20 + k0 + tig];
                ah[1] = sA[(row + 8) * 20 + k0 + tig];
                ah[2] = sA[row * 20 + k0 + tig + 4];
                ah[3] = sA[(row + 8) * 20 + k0 + tig + 4];
                al[0] = sA[2560 + row * 20 + k0 + tig];
                al[1] = sA[2560 + (row + 8) * 20 + k0 + tig];
                al[2] = sA[2560 + row * 20 + k0 + tig + 4];
                al[3] = sA[2560 + (row + 8) * 20 + k0 + tig + 4];
#pragma unroll
                for (int nf = 0; nf < 4; nf++) {
                    MMA_TF32(c[mf][nf], ah, bh[nf]);
                    MMA_TF32(c[mf][nf], al, bh[nf]);
                    MMA_TF32(c[mf][nf], ah, bl[nf]);
                }
            }
        }
        __syncthreads();

        if (kt + 2 < KT) issue(kt + 2);
        CP_COMMIT();
    }

    // epilogue
#pragma unroll
    for (int mf = 0; mf < 4; mf++) {
#pragma unroll
        for (int nf = 0; nf < 4; nf++) {
            const int row = brow + (wm << 6) + (mf << 4) + group;
            const int col = bcol + (wn << 5) + (nf << 3) + (tig << 1);
            float bx = 0.f, by = 0.f;
            if (HASBIAS) { bx = __ldg(bias + col); by = __ldg(bias + col + 1); }
            float2 o0, o1;
            o0.x = c[mf][nf][0] + bx;  o0.y = c[mf][nf][1] + by;
            o1.x = c[mf][nf][2] + bx;  o1.y = c[mf][nf][3] + by;
            if (RELU) {
                o0.x = fmaxf(o0.x, 0.f); o0.y = fmaxf(o0.y, 0.f);
                o1.x = fmaxf(o1.x, 0.f); o1.y = fmaxf(o1.y, 0.f);
            }
            if (OSPLIT) {
                float2 h0, h1, l0, l1;
                h0.x = tf32f(o0.x); l0.x = tf32f(o0.x - h0.x);
                h0.y = tf32f(o0.y); l0.y = tf32f(o0.y - h0.y);
                h1.x = tf32f(o1.x); l1.x = tf32f(o1.x - h1.x);
                h1.y = tf32f(o1.y); l1.y = tf32f(o1.y - h1.y);
                *(float2*)(C  + (size_t)row * M + col)       = h0;
                *(float2*)(C  + (size_t)(row + 8) * M + col) = h1;
                *(float2*)(Cl + (size_t)row * M + col)       = l0;
                *(float2*)(Cl + (size_t)(row + 8) * M + col) = l1;
            } else {
                *(float2*)(C + (size_t)row * M + col)       = o0;
                *(float2*)(C + (size_t)(row + 8) * M + col) = o1;
            }
        }
    }
}

// ---------------- prep: cb split + csq + commit=0 --------------------------
// blocks 0..511: split codebook elements; blocks 512..513: csq rows.
__global__ void prep_kernel(const float* __restrict__ cb) {
    const int b = blockIdx.x;
    const int t = threadIdx.x;
    if (b < 512) {
        int idx = b * 256 + t;                 // 512*256 = 131072 elems
        float v = cb[idx];
        float h = tf32f(v);
        g_cbH[idx] = h;
        g_cbL[idx] = tf32f(v - h);
    } else {
        int k = (b - 512) * 256 + t;           // code row
        if (b == 512 && t == 0) g_commit = 0.0;
        const float* row = cb + (size_t)k * CBD;
        float s = 0.f;
#pragma unroll 8
        for (int c = 0; c < CBD; c += 4) {
            float4 v = *(const float4*)(row + c);
            s += v.x*v.x + v.y*v.y + v.z*v.z + v.w*v.w;
        }
        g_csq[k] = s;
    }
}

// ---------------- transpose + split: W[K,M] -> WTh/WTl[M,K] ----------------
__global__ void transpose_split(const float* __restrict__ W,
                                float* __restrict__ WTh, float* __restrict__ WTl,
                                int K, int M) {
    int idx = blockIdx.x * 256 + threadIdx.x;
    if (idx < K * M) {
        int m = idx / K, k = idx - m * K;
        float v = W[(size_t)k * M + m];
        float h = tf32f(v);
        WTh[idx] = h;
        WTl[idx] = tf32f(v - h);
    }
}

// ---------------- fp32 SGEMM for the tiny decoder-table GEMMs -------------
template<bool RELU, bool HASBIAS>
__global__ void __launch_bounds__(256) sgemm_kernel(
    const float* __restrict__ A, const float* __restrict__ B,
    const float* __restrict__ bias, float* __restrict__ C,
    int N, int K, int M)
{
    __shared__ float As[16][132];
    __shared__ float Bs[16][72];
    const int tid  = threadIdx.x;
    const int tx   = tid & 15;
    const int ty   = tid >> 4;
    const int brow = blockIdx.y << 7;
    const int bcol = blockIdx.x << 6;

    const int ar = tid >> 2;
    const int ac = (tid & 3) << 2;
    const float* a0 = A + (size_t)(brow + ar) * K + ac;
    const float* a1 = A + (size_t)(brow + ar + 64) * K + ac;
    const int br = tid >> 4;
    const int bc = (tid & 15) << 2;
    const float* bptr = B + (size_t)br * M + bcol + bc;

    float acc[8][4];
#pragma unroll
    for (int i = 0; i < 8; i++)
#pragma unroll
        for (int j = 0; j < 4; j++) acc[i][j] = 0.f;

    for (int k0 = 0; k0 < K; k0 += 16) {
        float4 av0 = *(const float4*)(a0 + k0);
        float4 av1 = *(const float4*)(a1 + k0);
        float4 bv  = *(const float4*)(bptr + (size_t)k0 * M);
        As[ac + 0][ar] = av0.x;  As[ac + 1][ar] = av0.y;
        As[ac + 2][ar] = av0.z;  As[ac + 3][ar] = av0.w;
        As[ac + 0][ar + 64] = av1.x;  As[ac + 1][ar + 64] = av1.y;
        As[ac + 2][ar + 64] = av1.z;  As[ac + 3][ar + 64] = av1.w;
        *(float4*)&Bs[br][bc] = bv;
        __syncthreads();
#pragma unroll
        for (int kk = 0; kk < 16; kk++) {
            float4 a4l = *(const float4*)&As[kk][ty << 3];
            float4 a4h = *(const float4*)&As[kk][(ty << 3) + 4];
            float4 b4  = *(const float4*)&Bs[kk][tx << 2];
            float arr[8] = {a4l.x, a4l.y, a4l.z, a4l.w, a4h.x, a4h.y, a4h.z, a4h.w};
            float brr[4] = {b4.x, b4.y, b4.z, b4.w};
#pragma unroll
            for (int i = 0; i < 8; i++)
#pragma unroll
                for (int j = 0; j < 4; j++)
                    acc[i][j] = fmaf(arr[i], brr[j], acc[i][j]);
        }
        __syncthreads();
    }

    float4 bb = make_float4(0.f, 0.f, 0.f, 0.f);
    if (HASBIAS) bb = *(const float4*)(bias + bcol + (tx << 2));
#pragma unroll
    for (int i = 0; i < 8; i++) {
        float4 o;
        o.x = acc[i][0] + bb.x;
        o.y = acc[i][1] + bb.y;
        o.z = acc[i][2] + bb.z;
        o.w = acc[i][3] + bb.w;
        if (RELU) {
            o.x = fmaxf(o.x, 0.f); o.y = fmaxf(o.y, 0.f);
            o.z = fmaxf(o.z, 0.f); o.w = fmaxf(o.w, 0.f);
        }
        *(float4*)(C + (size_t)(brow + (ty << 3) + i) * M + bcol + (tx << 2)) = o;
    }
}

// ---- VQ: argmin + commit partial + recon gather from decoder table -------
__global__ void __launch_bounds__(256) vq_recon_kernel(
    const float* __restrict__ dots,
    const float* __restrict__ zH, const float* __restrict__ zL,
    const float* __restrict__ R, float* __restrict__ out_idx,
    float* __restrict__ out_recon)
{
    __shared__ float s_csq[CBK];
    __shared__ float s_part[8];
    const int tid = threadIdx.x;
    s_csq[tid]       = g_csq[tid];
    s_csq[tid + 256] = g_csq[tid + 256];
    __syncthreads();

    const int token = (blockIdx.x << 6) + (tid >> 2);
    const int part  = tid & 3;
    const int kbase = part << 7;

    const float4* drow = (const float4*)(dots + (size_t)token * CBK + kbase);
    float best = 3.4e38f;
    int   bidx = kbase;
#pragma unroll 8
    for (int i = 0; i < 32; i++) {
        float4 d4 = drow[i];
        int k = kbase + (i << 2);
        float v;
        v = s_csq[k + 0] - 2.f * d4.x; if (v < best) { best = v; bidx = k + 0; }
        v = s_csq[k + 1] - 2.f * d4.y; if (v < best) { best = v; bidx = k + 1; }
        v = s_csq[k + 2] - 2.f * d4.z; if (v < best) { best = v; bidx = k + 2; }
        v = s_csq[k + 3] - 2.f * d4.w; if (v < best) { best = v; bidx = k + 3; }
    }
#pragma unroll
    for (int off = 1; off < 4; off <<= 1) {
        float ob = __shfl_xor_sync(0xffffffffu, best, off);
        int   oi = __shfl_xor_sync(0xffffffffu, bidx, off);
        if (ob < best || (ob == best && oi < bidx)) { best = ob; bidx = oi; }
    }

    // ||z||^2 from split planes (z = zH + zL)
    const float4* zh = (const float4*)(zH + (size_t)token * CBD + (part << 6));
    const float4* zl = (const float4*)(zL + (size_t)token * CBD + (part << 6));
    float s = 0.f;
#pragma unroll
    for (int i = 0; i < 16; i++) {
        float4 a = zh[i], b = zl[i];
        float vx = a.x + b.x, vy = a.y + b.y, vz = a.z + b.z, vw = a.w + b.w;
        s += vx*vx + vy*vy + vz*vz + vw*vw;
    }
    s += __shfl_xor_sync(0xffffffffu, s, 1);
    s += __shfl_xor_sync(0xffffffffu, s, 2);

    float cv = (part == 0) ? (s + best) : 0.f;
    if (part == 0) out_idx[token] = (float)bidx;

    const float4* src = (const float4*)(R + (size_t)bidx * D_IN + part * 192);
    float4*       dst = (float4*)(out_recon + (size_t)token * D_IN + part * 192);
#pragma unroll 4
    for (int i = 0; i < 48; i++) dst[i] = src[i];

#pragma unroll
    for (int off = 16; off; off >>= 1) cv += __shfl_xor_sync(0xffffffffu, cv, off);
    if ((tid & 31) == 0) s_part[tid >> 5] = cv;
    __syncthreads();
    if (tid == 0) {
        float t = 0.f;
#pragma unroll
        for (int w = 0; w < 8; w++) t += s_part[w];
        atomicAdd(&g_commit, (double)t);
    }
}

__global__ void finalize_kernel(float* __restrict__ out_loss) {
    *out_loss = (float)(g_commit * (1.0 / ((double)NTOK * CBD)));
}

// ---------------- launch ---------------------------------------------------
#define MMA_SMEM 81920

extern "C" void kernel_launch(void* const* d_in, const int* in_sizes, int n_in,
                              void* d_out, int out_size) {
    const float* x  = (const float*)d_in[0];
    const float* W1 = (const float*)d_in[1];
    const float* b1 = (const float*)d_in[2];
    const float* W2 = (const float*)d_in[3];
    const float* b2 = (const float*)d_in[4];
    const float* cb = (const float*)d_in[5];
    const float* W3 = (const float*)d_in[6];
    const float* b3 = (const float*)d_in[7];
    const float* W4 = (const float*)d_in[8];
    const float* b4 = (const float*)d_in[9];

    float* out       = (float*)d_out;
    float* out_recon = out;
    float* out_idx   = out + (size_t)NTOK * D_IN;
    float* out_loss  = out_idx + NTOK;

    float *phH, *phL, *pzH, *pzL, *pdots, *pT1, *pR;
    float *pW1TH, *pW1TL, *pW2TH, *pW2TL, *pcbH, *pcbL;
    cudaGetSymbolAddress((void**)&phH,   g_hH);
    cudaGetSymbolAddress((void**)&phL,   g_hL);
    cudaGetSymbolAddress((void**)&pzH,   g_zH);
    cudaGetSymbolAddress((void**)&pzL,   g_zL);
    cudaGetSymbolAddress((void**)&pdots, g_dots);
    cudaGetSymbolAddress((void**)&pT1,   g_T1);
    cudaGetSymbolAddress((void**)&pR,    g_R);
    cudaGetSymbolAddress((void**)&pW1TH, g_W1TH);
    cudaGetSymbolAddress((void**)&pW1TL, g_W1TL);
    cudaGetSymbolAddress((void**)&pW2TH, g_W2TH);
    cudaGetSymbolAddress((void**)&pW2TL, g_W2TL);
    cudaGetSymbolAddress((void**)&pcbH,  g_cbH);
    cudaGetSymbolAddress((void**)&pcbL,  g_cbL);

    static bool attr_done = false;
    if (!attr_done) {
        cudaFuncSetAttribute(mma_gemm<true,  true,  false, true >,
                             cudaFuncAttributeMaxDynamicSharedMemorySize, MMA_SMEM);
        cudaFuncSetAttribute(mma_gemm<false, true,  true,  true >,
                             cudaFuncAttributeMaxDynamicSharedMemorySize, MMA_SMEM);
        cudaFuncSetAttribute(mma_gemm<false, false, true,  false>,
                             cudaFuncAttributeMaxDynamicSharedMemorySize, MMA_SMEM);
        attr_done = true;
    }

    // [0] prep: cb split + csq + commit=0
    prep_kernel<<<514, 256>>>(cb);
    // [1][2] weight transpose+split
    transpose_split<<<(HID * D_IN + 255) / 256, 256>>>(W1, pW1TH, pW1TL, D_IN, HID);
    transpose_split<<<(CBD * HID + 255) / 256, 256>>>(W2, pW2TH, pW2TL, HID, CBD);
    // [3] h = relu(x @ W1 + b1), split output   (ncu-captured slot)
    mma_gemm<true,  true,  false, true ><<<dim3(HID / 128, NTOK / 128), 256, MMA_SMEM>>>(
        x, nullptr, pW1TH, pW1TL, b1, phH, phL, D_IN, HID);
    // [4][5] decoder table (tiny, fp32)
    sgemm_kernel<true , true ><<<dim3(HID  / 64, 512 / 128), 256>>>(cb,  W3, b3, pT1, 512, CBD, HID);
    sgemm_kernel<false, true ><<<dim3(D_IN / 64, 512 / 128), 256>>>(pT1, W4, b4, pR,  512, HID, D_IN);
    // [6] z = h @ W2 + b2, split output
    mma_gemm<false, true,  true,  true ><<<dim3(CBD / 128, NTOK / 128), 256, MMA_SMEM>>>(
        phH, phL, pW2TH, pW2TL, b2, pzH, pzL, HID, CBD);
    // [7] dots = z @ cb^T, plain output
    mma_gemm<false, false, true,  false><<<dim3(CBK / 128, NTOK / 128), 256, MMA_SMEM>>>(
        pzH, pzL, pcbH, pcbL, nullptr, pdots, nullptr, CBD, CBK);
    // [8] argmin + indices + commit + recon gather
    vq_recon_kernel<<<NTOK / 64, 256>>>(pdots, pzH, pzL, pR, out_idx, out_recon);
    // [9] loss
    finalize_kernel<<<1, 1>>>(out_loss);
}

// round 7
// speedup vs baseline: 3.5898x; 1.5143x over previous
#include <cuda_runtime.h>
#include <cuda_fp16.h>
#include <cstdint>

#define NTOK 65536
#define D_IN 768
#define HID  512
#define CBD  256
#define CBK  512

// ---------------- scratch (device globals; no allocations) ----------------
__device__ __half g_xh[(size_t)NTOK * D_IN];
__device__ __half g_xl[(size_t)NTOK * D_IN];
__device__ __half g_hH[(size_t)NTOK * HID];
__device__ __half g_hL[(size_t)NTOK * HID];
__device__ __half g_zH[(size_t)NTOK * CBD];
__device__ __half g_zL[(size_t)NTOK * CBD];
__device__ float  g_dots[(size_t)NTOK * CBK];
__device__ __half g_W1TH[HID * D_IN];
__device__ __half g_W1TL[HID * D_IN];
__device__ __half g_W2TH[CBD * HID];
__device__ __half g_W2TL[CBD * HID];
__device__ __half g_cbH[CBK * CBD];
__device__ __half g_cbL[CBK * CBD];
__device__ float  g_T1[512 * 512];
__device__ float  g_R[512 * 768];
__device__ float  g_csq[CBK];
__device__ double g_commit;

// ---------------- helpers --------------------------------------------------
__device__ __forceinline__ void split_h(float v, __half& h, __half& l) {
    h = __float2half_rn(v);
    l = __float2half_rn(v - __half2float(h));
}
__device__ __forceinline__ void cp16(uint32_t saddr, const void* g) {
    asm volatile("cp.async.cg.shared.global [%0], [%1], 16;" :: "r"(saddr), "l"(g));
}
#define CP_COMMIT() asm volatile("cp.async.commit_group;" ::: "memory")
#define CP_WAIT1()  asm volatile("cp.async.wait_group 1;" ::: "memory")

#define LDSM4(r0, r1, r2, r3, addr) \
    asm volatile("ldmatrix.sync.aligned.m8n8.x4.shared.b16 {%0,%1,%2,%3}, [%4];" \
        : "=r"(r0), "=r"(r1), "=r"(r2), "=r"(r3) : "r"(addr))

#define MMA16(cc, aa, bb) \
    asm volatile("mma.sync.aligned.m16n8k16.row.col.f32.f16.f16.f32 " \
        "{%0,%1,%2,%3}, {%4,%5,%6,%7}, {%8,%9}, {%0,%1,%2,%3};" \
        : "+f"((cc)[0]), "+f"((cc)[1]), "+f"((cc)[2]), "+f"((cc)[3]) \
        : "r"((aa)[0]), "r"((aa)[1]), "r"((aa)[2]), "r"((aa)[3]), \
          "r"((bb)[0]), "r"((bb)[1]))

// =================== fp16 3x-split HMMA GEMM ===============================
// C[N, M] = op((Ah+Al)[N,K] @ (Bh+Bl)^T + bias); planes are __half [.,K] rowmaj.
// CTA tile 128x128, 8 warps each 64x32, K-tile 16, 3-stage cp.async pipeline.
// Stage (bytes): Ah@0, Al@6144, Bh@12288, Bl@18432; row stride 48B (24 halves).
#define STAGE_B  24576
#define HSMEM    (3 * STAGE_B)

template<bool RELU, bool HASBIAS, bool OSPLIT>
__global__ void __launch_bounds__(256, 2) hmma_gemm(
    const __half* __restrict__ Ah, const __half* __restrict__ Al,
    const __half* __restrict__ Bh, const __half* __restrict__ Bl,
    const float* __restrict__ bias,
    float* __restrict__ C, __half* __restrict__ Ch, __half* __restrict__ Cl,
    int K, int M)
{
    extern __shared__ char hsm[];
    uint32_t sbase;
    asm("{ .reg .u64 t; cvta.to.shared.u64 t, %1; cvt.u32.u64 %0, t; }"
        : "=r"(sbase) : "l"(hsm));

    const int tid  = threadIdx.x;
    const int lane = tid & 31;
    const int wid  = tid >> 5;
    const int wm   = wid & 1;
    const int wn   = wid >> 1;
    const int group = lane >> 2;
    const int tig   = lane & 3;
    const int brow = blockIdx.y << 7;
    const int bcol = blockIdx.x << 7;

    // loader: thread -> (row, 16B chunk)
    const int lrow = tid >> 1;
    const int lchk = tid & 1;
    const uint32_t soff = sbase + (uint32_t)(lrow * 48 + lchk * 16);
    const __half* gAh = Ah + (size_t)(brow + lrow) * K + lchk * 8;
    const __half* gAl = Al + (size_t)(brow + lrow) * K + lchk * 8;
    const __half* gBh = Bh + (size_t)(bcol + lrow) * K + lchk * 8;
    const __half* gBl = Bl + (size_t)(bcol + lrow) * K + lchk * 8;

    // ldmatrix lane offsets (bytes)
    const uint32_t aoff = (uint32_t)(((lane & 15) * 24 + (lane >> 4) * 8) * 2);
    const uint32_t boff = (uint32_t)((((lane & 7) + ((lane >> 4) << 3)) * 24 +
                                      ((lane >> 3) & 1) * 8) * 2);

    float c[4][4][4];
#pragma unroll
    for (int i = 0; i < 4; i++)
#pragma unroll
        for (int j = 0; j < 4; j++)
#pragma unroll
            for (int k = 0; k < 4; k++) c[i][j][k] = 0.f;

    const int KT = K >> 4;
    auto issue = [&](int kt) {
        const uint32_t sb = soff + (uint32_t)(kt % 3) * STAGE_B;
        const size_t go = (size_t)kt << 4;
        cp16(sb,         gAh + go);
        cp16(sb + 6144,  gAl + go);
        cp16(sb + 12288, gBh + go);
        cp16(sb + 18432, gBl + go);
    };

    issue(0); CP_COMMIT();
    issue(1); CP_COMMIT();

    for (int kt = 0; kt < KT; kt++) {
        CP_WAIT1();
        __syncthreads();
        if (kt + 2 < KT) issue(kt + 2);
        CP_COMMIT();

        const uint32_t st = sbase + (uint32_t)(kt % 3) * STAGE_B;

        // B fragments: pairs (nf0,nf1) and (nf2,nf3), hi and lo planes
        uint32_t bh[4][2], bl[4][2];
        {
            const uint32_t b0 = st + 12288 + (uint32_t)((wn << 5) * 48) + boff;
            const uint32_t b1 = b0 + 16 * 48;
            LDSM4(bh[0][0], bh[0][1], bh[1][0], bh[1][1], b0);
            LDSM4(bh[2][0], bh[2][1], bh[3][0], bh[3][1], b1);
            LDSM4(bl[0][0], bl[0][1], bl[1][0], bl[1][1], b0 + 6144);
            LDSM4(bl[2][0], bl[2][1], bl[3][0], bl[3][1], b1 + 6144);
        }
#pragma unroll
        for (int mf = 0; mf < 4; mf++) {
            const uint32_t a0 = st + (uint32_t)(((wm << 6) + (mf << 4)) * 48) + aoff;
            uint32_t ah[4], al[4];
            LDSM4(ah[0], ah[1], ah[2], ah[3], a0);
            LDSM4(al[0], al[1], al[2], al[3], a0 + 6144);
#pragma unroll
            for (int nf = 0; nf < 4; nf++) MMA16(c[mf][nf], ah, bh[nf]);
#pragma unroll
            for (int nf = 0; nf < 4; nf++) MMA16(c[mf][nf], al, bh[nf]);
#pragma unroll
            for (int nf = 0; nf < 4; nf++) MMA16(c[mf][nf], ah, bl[nf]);
        }
    }

    // epilogue
#pragma unroll
    for (int mf = 0; mf < 4; mf++) {
#pragma unroll
        for (int nf = 0; nf < 4; nf++) {
            const int row = brow + (wm << 6) + (mf << 4) + group;
            const int col = bcol + (wn << 5) + (nf << 3) + (tig << 1);
            float bx = 0.f, by = 0.f;
            if (HASBIAS) { bx = __ldg(bias + col); by = __ldg(bias + col + 1); }
            float2 o0, o1;
            o0.x = c[mf][nf][0] + bx;  o0.y = c[mf][nf][1] + by;
            o1.x = c[mf][nf][2] + bx;  o1.y = c[mf][nf][3] + by;
            if (RELU) {
                o0.x = fmaxf(o0.x, 0.f); o0.y = fmaxf(o0.y, 0.f);
                o1.x = fmaxf(o1.x, 0.f); o1.y = fmaxf(o1.y, 0.f);
            }
            if (OSPLIT) {
                __half hx, lx, hy, ly;
                split_h(o0.x, hx, lx); split_h(o0.y, hy, ly);
                *(__half2*)(Ch + (size_t)row * M + col) = __halves2half2(hx, hy);
                *(__half2*)(Cl + (size_t)row * M + col) = __halves2half2(lx, ly);
                split_h(o1.x, hx, lx); split_h(o1.y, hy, ly);
                *(__half2*)(Ch + (size_t)(row + 8) * M + col) = __halves2half2(hx, hy);
                *(__half2*)(Cl + (size_t)(row + 8) * M + col) = __halves2half2(lx, ly);
            } else {
                *(float2*)(C + (size_t)row * M + col)       = o0;
                *(float2*)(C + (size_t)(row + 8) * M + col) = o1;
            }
        }
    }
}

// ---------------- prep: cb split + csq + commit=0 --------------------------
__global__ void prep_kernel(const float* __restrict__ cb) {
    const int b = blockIdx.x;
    const int t = threadIdx.x;
    if (b < 512) {
        int idx = b * 256 + t;
        __half h, l;
        split_h(cb[idx], h, l);
        g_cbH[idx] = h;
        g_cbL[idx] = l;
    } else {
        int k = (b - 512) * 256 + t;
        if (b == 512 && t == 0) g_commit = 0.0;
        const float* row = cb + (size_t)k * CBD;
        float s = 0.f;
#pragma unroll 8
        for (int c = 0; c < CBD; c += 4) {
            float4 v = *(const float4*)(row + c);
            s += v.x*v.x + v.y*v.y + v.z*v.z + v.w*v.w;
        }
        g_csq[k] = s;
    }
}

// ---------------- split x into fp16 hi/lo planes ---------------------------
__global__ void split_x_kernel(const float* __restrict__ x) {
    size_t i = ((size_t)blockIdx.x * 256 + threadIdx.x) * 4;
    float4 v = *(const float4*)(x + i);
    __half h0, l0, h1, l1, h2, l2, h3, l3;
    split_h(v.x, h0, l0); split_h(v.y, h1, l1);
    split_h(v.z, h2, l2); split_h(v.w, h3, l3);
    *(__half2*)(g_xh + i)     = __halves2half2(h0, h1);
    *(__half2*)(g_xh + i + 2) = __halves2half2(h2, h3);
    *(__half2*)(g_xl + i)     = __halves2half2(l0, l1);
    *(__half2*)(g_xl + i + 2) = __halves2half2(l2, l3);
}

// ---------------- transpose + split: W[K,M] -> half planes [M,K] -----------
__global__ void transpose_split(const float* __restrict__ W,
                                __half* __restrict__ WTh, __half* __restrict__ WTl,
                                int K, int M) {
    int idx = blockIdx.x * 256 + threadIdx.x;
    if (idx < K * M) {
        int m = idx / K, k = idx - m * K;
        __half h, l;
        split_h(W[(size_t)k * M + m], h, l);
        WTh[idx] = h;
        WTl[idx] = l;
    }
}

// ---------------- fp32 SGEMM for the tiny decoder-table GEMMs -------------
template<bool RELU, bool HASBIAS>
__global__ void __launch_bounds__(256) sgemm_kernel(
    const float* __restrict__ A, const float* __restrict__ B,
    const float* __restrict__ bias, float* __restrict__ C,
    int N, int K, int M)
{
    __shared__ float As[16][132];
    __shared__ float Bs[16][72];
    const int tid  = threadIdx.x;
    const int tx   = tid & 15;
    const int ty   = tid >> 4;
    const int brow = blockIdx.y << 7;
    const int bcol = blockIdx.x << 6;

    const int ar = tid >> 2;
    const int ac = (tid & 3) << 2;
    const float* a0 = A + (size_t)(brow + ar) * K + ac;
    const float* a1 = A + (size_t)(brow + ar + 64) * K + ac;
    const int br = tid >> 4;
    const int bc = (tid & 15) << 2;
    const float* bptr = B + (size_t)br * M + bcol + bc;

    float acc[8][4];
#pragma unroll
    for (int i = 0; i < 8; i++)
#pragma unroll
        for (int j = 0; j < 4; j++) acc[i][j] = 0.f;

    for (int k0 = 0; k0 < K; k0 += 16) {
        float4 av0 = *(const float4*)(a0 + k0);
        float4 av1 = *(const float4*)(a1 + k0);
        float4 bv  = *(const float4*)(bptr + (size_t)k0 * M);
        As[ac + 0][ar] = av0.x;  As[ac + 1][ar] = av0.y;
        As[ac + 2][ar] = av0.z;  As[ac + 3][ar] = av0.w;
        As[ac + 0][ar + 64] = av1.x;  As[ac + 1][ar + 64] = av1.y;
        As[ac + 2][ar + 64] = av1.z;  As[ac + 3][ar + 64] = av1.w;
        *(float4*)&Bs[br][bc] = bv;
        __syncthreads();
#pragma unroll
        for (int kk = 0; kk < 16; kk++) {
            float4 a4l = *(const float4*)&As[kk][ty << 3];
            float4 a4h = *(const float4*)&As[kk][(ty << 3) + 4];
            float4 b4  = *(const float4*)&Bs[kk][tx << 2];
            float arr[8] = {a4l.x, a4l.y, a4l.z, a4l.w, a4h.x, a4h.y, a4h.z, a4h.w};
            float brr[4] = {b4.x, b4.y, b4.z, b4.w};
#pragma unroll
            for (int i = 0; i < 8; i++)
#pragma unroll
                for (int j = 0; j < 4; j++)
                    acc[i][j] = fmaf(arr[i], brr[j], acc[i][j]);
        }
        __syncthreads();
    }

    float4 bb = make_float4(0.f, 0.f, 0.f, 0.f);
    if (HASBIAS) bb = *(const float4*)(bias + bcol + (tx << 2));
#pragma unroll
    for (int i = 0; i < 8; i++) {
        float4 o;
        o.x = acc[i][0] + bb.x;
        o.y = acc[i][1] + bb.y;
        o.z = acc[i][2] + bb.z;
        o.w = acc[i][3] + bb.w;
        if (RELU) {
            o.x = fmaxf(o.x, 0.f); o.y = fmaxf(o.y, 0.f);
            o.z = fmaxf(o.z, 0.f); o.w = fmaxf(o.w, 0.f);
        }
        *(float4*)(C + (size_t)(brow + (ty << 3) + i) * M + bcol + (tx << 2)) = o;
    }
}

// ---- VQ: argmin + commit partial + recon gather from decoder table -------
__global__ void __launch_bounds__(256) vq_recon_kernel(
    const float* __restrict__ dots,
    const __half* __restrict__ zH, const __half* __restrict__ zL,
    const float* __restrict__ R, float* __restrict__ out_idx,
    float* __restrict__ out_recon)
{
    __shared__ float s_csq[CBK];
    __shared__ float s_part[8];
    const int tid = threadIdx.x;
    s_csq[tid]       = g_csq[tid];
    s_csq[tid + 256] = g_csq[tid + 256];
    __syncthreads();

    const int token = (blockIdx.x << 6) + (tid >> 2);
    const int part  = tid & 3;
    const int kbase = part << 7;

    const float4* drow = (const float4*)(dots + (size_t)token * CBK + kbase);
    float best = 3.4e38f;
    int   bidx = kbase;
#pragma unroll 8
    for (int i = 0; i < 32; i++) {
        float4 d4 = drow[i];
        int k = kbase + (i << 2);
        float v;
        v = s_csq[k + 0] - 2.f * d4.x; if (v < best) { best = v; bidx = k + 0; }
        v = s_csq[k + 1] - 2.f * d4.y; if (v < best) { best = v; bidx = k + 1; }
        v = s_csq[k + 2] - 2.f * d4.z; if (v < best) { best = v; bidx = k + 2; }
        v = s_csq[k + 3] - 2.f * d4.w; if (v < best) { best = v; bidx = k + 3; }
    }
#pragma unroll
    for (int off = 1; off < 4; off <<= 1) {
        float ob = __shfl_xor_sync(0xffffffffu, best, off);
        int   oi = __shfl_xor_sync(0xffffffffu, bidx, off);
        if (ob < best || (ob == best && oi < bidx)) { best = ob; bidx = oi; }
    }

    // ||z||^2 from half planes (z = zH + zL); 64 coords per lane
    const __half2* zh2 = (const __half2*)(zH + (size_t)token * CBD + (part << 6));
    const __half2* zl2 = (const __half2*)(zL + (size_t)token * CBD + (part << 6));
    float s = 0.f;
#pragma unroll
    for (int i = 0; i < 32; i++) {
        float2 a = __half22float2(zh2[i]);
        float2 b = __half22float2(zl2[i]);
        float vx = a.x + b.x, vy = a.y + b.y;
        s += vx * vx + vy * vy;
    }
    s += __shfl_xor_sync(0xffffffffu, s, 1);
    s += __shfl_xor_sync(0xffffffffu, s, 2);

    float cv = (part == 0) ? (s + best) : 0.f;
    if (part == 0) out_idx[token] = (float)bidx;

    const float4* src = (const float4*)(R + (size_t)bidx * D_IN + part * 192);
    float4*       dst = (float4*)(out_recon + (size_t)token * D_IN + part * 192);
#pragma unroll 4
    for (int i = 0; i < 48; i++) dst[i] = src[i];

#pragma unroll
    for (int off = 16; off; off >>= 1) cv += __shfl_xor_sync(0xffffffffu, cv, off);
    if ((tid & 31) == 0) s_part[tid >> 5] = cv;
    __syncthreads();
    if (tid == 0) {
        float t = 0.f;
#pragma unroll
        for (int w = 0; w < 8; w++) t += s_part[w];
        atomicAdd(&g_commit, (double)t);
    }
}

__global__ void finalize_kernel(float* __restrict__ out_loss) {
    *out_loss = (float)(g_commit * (1.0 / ((double)NTOK * CBD)));
}

// ---------------- launch ---------------------------------------------------
extern "C" void kernel_launch(void* const* d_in, const int* in_sizes, int n_in,
                              void* d_out, int out_size) {
    const float* x  = (const float*)d_in[0];
    const float* W1 = (const float*)d_in[1];
    const float* b1 = (const float*)d_in[2];
    const float* W2 = (const float*)d_in[3];
    const float* b2 = (const float*)d_in[4];
    const float* cb = (const float*)d_in[5];
    const float* W3 = (const float*)d_in[6];
    const float* b3 = (const float*)d_in[7];
    const float* W4 = (const float*)d_in[8];
    const float* b4 = (const float*)d_in[9];

    float* out       = (float*)d_out;
    float* out_recon = out;
    float* out_idx   = out + (size_t)NTOK * D_IN;
    float* out_loss  = out_idx + NTOK;

    __half *pxh, *pxl, *phH, *phL, *pzH, *pzL;
    __half *pW1TH, *pW1TL, *pW2TH, *pW2TL, *pcbH, *pcbL;
    float *pdots, *pT1, *pR;
    cudaGetSymbolAddress((void**)&pxh,   g_xh);
    cudaGetSymbolAddress((void**)&pxl,   g_xl);
    cudaGetSymbolAddress((void**)&phH,   g_hH);
    cudaGetSymbolAddress((void**)&phL,   g_hL);
    cudaGetSymbolAddress((void**)&pzH,   g_zH);
    cudaGetSymbolAddress((void**)&pzL,   g_zL);
    cudaGetSymbolAddress((void**)&pdots, g_dots);
    cudaGetSymbolAddress((void**)&pT1,   g_T1);
    cudaGetSymbolAddress((void**)&pR,    g_R);
    cudaGetSymbolAddress((void**)&pW1TH, g_W1TH);
    cudaGetSymbolAddress((void**)&pW1TL, g_W1TL);
    cudaGetSymbolAddress((void**)&pW2TH, g_W2TH);
    cudaGetSymbolAddress((void**)&pW2TL, g_W2TL);
    cudaGetSymbolAddress((void**)&pcbH,  g_cbH);
    cudaGetSymbolAddress((void**)&pcbL,  g_cbL);

    static bool attr_done = false;
    if (!attr_done) {
        cudaFuncSetAttribute(hmma_gemm<true,  true,  true >,
                             cudaFuncAttributeMaxDynamicSharedMemorySize, HSMEM);
        cudaFuncSetAttribute(hmma_gemm<false, true,  true >,
                             cudaFuncAttributeMaxDynamicSharedMemorySize, HSMEM);
        cudaFuncSetAttribute(hmma_gemm<false, false, false>,
                             cudaFuncAttributeMaxDynamicSharedMemorySize, HSMEM);
        attr_done = true;
    }

    // [0] prep: cb split + csq + commit=0
    prep_kernel<<<514, 256>>>(cb);
    // [1] split x into fp16 planes
    split_x_kernel<<<(NTOK * D_IN / 4) / 256, 256>>>(x);
    // [2] W1 transpose+split
    transpose_split<<<(HID * D_IN + 255) / 256, 256>>>(W1, pW1TH, pW1TL, D_IN, HID);
    // [3] h = relu(x @ W1 + b1), split output   (ncu-captured slot)
    hmma_gemm<true,  true,  true ><<<dim3(HID / 128, NTOK / 128), 256, HSMEM>>>(
        pxh, pxl, pW1TH, pW1TL, b1, nullptr, phH, phL, D_IN, HID);
    // [4] W2 transpose+split
    transpose_split<<<(CBD * HID + 255) / 256, 256>>>(W2, pW2TH, pW2TL, HID, CBD);
    // [5][6] decoder table (tiny, fp32)
    sgemm_kernel<true , true ><<<dim3(HID  / 64, 512 / 128), 256>>>(cb,  W3, b3, pT1, 512, CBD, HID);
    sgemm_kernel<false, true ><<<dim3(D_IN / 64, 512 / 128), 256>>>(pT1, W4, b4, pR,  512, HID, D_IN);
    // [7] z = h @ W2 + b2, split output
    hmma_gemm<false, true,  true ><<<dim3(CBD / 128, NTOK / 128), 256, HSMEM>>>(
        phH, phL, pW2TH, pW2TL, b2, nullptr, pzH, pzL, HID, CBD);
    // [8] dots = z @ cb^T, fp32 output
    hmma_gemm<false, false, false><<<dim3(CBK / 128, NTOK / 128), 256, HSMEM>>>(
        pzH, pzL, pcbH, pcbL, nullptr, pdots, nullptr, nullptr, CBD, CBK);
    // [9] argmin + indices + commit + recon gather
    vq_recon_kernel<<<NTOK / 64, 256>>>(pdots, pzH, pzL, pR, out_idx, out_recon);
    // [10] loss
    finalize_kernel<<<1, 1>>>(out_loss);
}

// round 8
// speedup vs baseline: 3.7839x; 1.0541x over previous
#include <cuda_runtime.h>
#include <cuda_fp16.h>
#include <cstdint>

#define NTOK 65536
#define D_IN 768
#define HID  512
#define CBD  256
#define CBK  512

// ---------------- scratch (device globals; no allocations) ----------------
__device__ __half g_xh[(size_t)NTOK * D_IN];
__device__ __half g_xl[(size_t)NTOK * D_IN];
__device__ __half g_hH[(size_t)NTOK * HID];
__device__ __half g_hL[(size_t)NTOK * HID];
__device__ __half g_zH[(size_t)NTOK * CBD];
__device__ __half g_zL[(size_t)NTOK * CBD];
__device__ float2 g_part[(size_t)NTOK * 4];   // per-128-code-block (val, idx)
__device__ __half g_W1TH[HID * D_IN];
__device__ __half g_W1TL[HID * D_IN];
__device__ __half g_W2TH[CBD * HID];
__device__ __half g_W2TL[CBD * HID];
__device__ __half g_cbH[CBK * CBD];
__device__ __half g_cbL[CBK * CBD];
__device__ float  g_T1[512 * 512];
__device__ float  g_R[512 * 768];
__device__ float  g_csq[CBK];
__device__ double g_commit;

// ---------------- helpers --------------------------------------------------
__device__ __forceinline__ void split_h(float v, __half& h, __half& l) {
    h = __float2half_rn(v);
    l = __float2half_rn(v - __half2float(h));
}
__device__ __forceinline__ void cp16(uint32_t saddr, const void* g) {
    asm volatile("cp.async.cg.shared.global [%0], [%1], 16;" :: "r"(saddr), "l"(g));
}
#define CP_COMMIT() asm volatile("cp.async.commit_group;" ::: "memory")
#define CP_WAIT2()  asm volatile("cp.async.wait_group 2;" ::: "memory")

#define LDSM4(r0, r1, r2, r3, addr) \
    asm volatile("ldmatrix.sync.aligned.m8n8.x4.shared.b16 {%0,%1,%2,%3}, [%4];" \
        : "=r"(r0), "=r"(r1), "=r"(r2), "=r"(r3) : "r"(addr))

#define MMA16(cc, aa, bb) \
    asm volatile("mma.sync.aligned.m16n8k16.row.col.f32.f16.f16.f32 " \
        "{%0,%1,%2,%3}, {%4,%5,%6,%7}, {%8,%9}, {%0,%1,%2,%3};" \
        : "+f"((cc)[0]), "+f"((cc)[1]), "+f"((cc)[2]), "+f"((cc)[3]) \
        : "r"((aa)[0]), "r"((aa)[1]), "r"((aa)[2]), "r"((aa)[3]), \
          "r"((bb)[0]), "r"((bb)[1]))

// =================== fp16 3x-split HMMA GEMM ===============================
// C[N, M] = op((Ah+Al)[N,K] @ (Bh+Bl)^T + bias); planes are __half [.,K] rowmaj.
// CTA tile 128x128, 8 warps each 64x32, K-tile 16, 4-stage cp.async pipeline.
// Stage (bytes): Ah@0, Al@6144, Bh@12288, Bl@18432; row stride 48B (24 halves).
// ARGMIN: no C store; per-row argmin of (csq[col] - 2*acc) over the 128 cols,
// partials to part[token*4 + blockIdx.x].
#define STAGE_B  24576
#define HSMEM    (4 * STAGE_B)

template<bool RELU, bool HASBIAS, bool OSPLIT, bool ARGMIN>
__global__ void __launch_bounds__(256, 2) hmma_gemm(
    const __half* __restrict__ Ah, const __half* __restrict__ Al,
    const __half* __restrict__ Bh, const __half* __restrict__ Bl,
    const float* __restrict__ bias,
    float* __restrict__ C, __half* __restrict__ Ch, __half* __restrict__ Cl,
    float2* __restrict__ part, int K, int M)
{
    extern __shared__ char hsm[];
    __shared__ float2 red[2][64][4];
    uint32_t sbase;
    asm("{ .reg .u64 t; cvta.to.shared.u64 t, %1; cvt.u32.u64 %0, t; }"
        : "=r"(sbase) : "l"(hsm));

    const int tid  = threadIdx.x;
    const int lane = tid & 31;
    const int wid  = tid >> 5;
    const int wm   = wid & 1;
    const int wn   = wid >> 1;
    const int group = lane >> 2;
    const int tig   = lane & 3;
    const int brow = blockIdx.y << 7;
    const int bcol = blockIdx.x << 7;

    // loader: thread -> (row, 16B chunk)
    const int lrow = tid >> 1;
    const int lchk = tid & 1;
    const uint32_t soff = sbase + (uint32_t)(lrow * 48 + lchk * 16);
    const __half* gAh = Ah + (size_t)(brow + lrow) * K + lchk * 8;
    const __half* gAl = Al + (size_t)(brow + lrow) * K + lchk * 8;
    const __half* gBh = Bh + (size_t)(bcol + lrow) * K + lchk * 8;
    const __half* gBl = Bl + (size_t)(bcol + lrow) * K + lchk * 8;

    // ldmatrix lane offsets (bytes)
    const uint32_t aoff = (uint32_t)(((lane & 15) * 24 + (lane >> 4) * 8) * 2);
    const uint32_t boff = (uint32_t)((((lane & 7) + ((lane >> 4) << 3)) * 24 +
                                      ((lane >> 3) & 1) * 8) * 2);

    float c[4][4][4];
#pragma unroll
    for (int i = 0; i < 4; i++)
#pragma unroll
        for (int j = 0; j < 4; j++)
#pragma unroll
            for (int k = 0; k < 4; k++) c[i][j][k] = 0.f;

    const int KT = K >> 4;
    auto issue = [&](int kt) {
        const uint32_t sb = soff + (uint32_t)(kt & 3) * STAGE_B;
        const size_t go = (size_t)kt << 4;
        cp16(sb,         gAh + go);
        cp16(sb + 6144,  gAl + go);
        cp16(sb + 12288, gBh + go);
        cp16(sb + 18432, gBl + go);
    };

    issue(0); CP_COMMIT();
    issue(1); CP_COMMIT();
    issue(2); CP_COMMIT();

    for (int kt = 0; kt < KT; kt++) {
        CP_WAIT2();
        __syncthreads();
        if (kt + 3 < KT) issue(kt + 3);
        CP_COMMIT();

        const uint32_t st = sbase + (uint32_t)(kt & 3) * STAGE_B;

        uint32_t bh[4][2], bl[4][2];
        {
            const uint32_t b0 = st + 12288 + (uint32_t)((wn << 5) * 48) + boff;
            const uint32_t b1 = b0 + 16 * 48;
            LDSM4(bh[0][0], bh[0][1], bh[1][0], bh[1][1], b0);
            LDSM4(bh[2][0], bh[2][1], bh[3][0], bh[3][1], b1);
            LDSM4(bl[0][0], bl[0][1], bl[1][0], bl[1][1], b0 + 6144);
            LDSM4(bl[2][0], bl[2][1], bl[3][0], bl[3][1], b1 + 6144);
        }
#pragma unroll
        for (int mf = 0; mf < 4; mf++) {
            const uint32_t a0 = st + (uint32_t)(((wm << 6) + (mf << 4)) * 48) + aoff;
            uint32_t ah[4], al[4];
            LDSM4(ah[0], ah[1], ah[2], ah[3], a0);
            LDSM4(al[0], al[1], al[2], al[3], a0 + 6144);
#pragma unroll
            for (int nf = 0; nf < 4; nf++) MMA16(c[mf][nf], ah, bh[nf]);
#pragma unroll
            for (int nf = 0; nf < 4; nf++) MMA16(c[mf][nf], al, bh[nf]);
#pragma unroll
            for (int nf = 0; nf < 4; nf++) MMA16(c[mf][nf], ah, bl[nf]);
        }
    }

    if (ARGMIN) {
        // per-thread rows: (wm<<6)+(mf<<4)+group (+8). Cols: (wn<<5)+(nf<<3)+(tig<<1)+{0,1}
#pragma unroll
        for (int mf = 0; mf < 4; mf++) {
#pragma unroll
            for (int sub = 0; sub < 2; sub++) {
                float bv = 3.4e38f;
                int   bi = 0;
#pragma unroll
                for (int nf = 0; nf < 4; nf++) {
                    const int col = (wn << 5) + (nf << 3) + (tig << 1);
                    float d0 = __ldg(&g_csq[bcol + col])     - 2.f * c[mf][nf][sub * 2];
                    float d1 = __ldg(&g_csq[bcol + col + 1]) - 2.f * c[mf][nf][sub * 2 + 1];
                    if (d0 < bv || (d0 == bv && col < bi))     { bv = d0; bi = col; }
                    if (d1 < bv || (d1 == bv && col + 1 < bi)) { bv = d1; bi = col + 1; }
                }
#pragma unroll
                for (int off = 1; off < 4; off <<= 1) {
                    float ov = __shfl_xor_sync(0xffffffffu, bv, off);
                    int   oi = __shfl_xor_sync(0xffffffffu, bi, off);
                    if (ov < bv || (ov == bv && oi < bi)) { bv = ov; bi = oi; }
                }
                if (tig == 0)
                    red[wm][(mf << 4) + group + sub * 8][wn] =
                        make_float2(bv, __int_as_float(bi));
            }
        }
        __syncthreads();
        if (tid < 128) {
            const int wmb = tid >> 6, rl = tid & 63;
            float bv = 3.4e38f;
            int   bi = 0;
#pragma unroll
            for (int w = 0; w < 4; w++) {
                float2 e = red[wmb][rl][w];
                int ei = __float_as_int(e.y);
                if (e.x < bv || (e.x == bv && ei < bi)) { bv = e.x; bi = ei; }
            }
            const int token = brow + (wmb << 6) + rl;
            part[(size_t)token * 4 + blockIdx.x] = make_float2(bv, (float)(bcol + bi));
        }
        return;
    }

    // normal epilogue
#pragma unroll
    for (int mf = 0; mf < 4; mf++) {
#pragma unroll
        for (int nf = 0; nf < 4; nf++) {
            const int row = brow + (wm << 6) + (mf << 4) + group;
            const int col = bcol + (wn << 5) + (nf << 3) + (tig << 1);
            float bx = 0.f, by = 0.f;
            if (HASBIAS) { bx = __ldg(bias + col); by = __ldg(bias + col + 1); }
            float2 o0, o1;
            o0.x = c[mf][nf][0] + bx;  o0.y = c[mf][nf][1] + by;
            o1.x = c[mf][nf][2] + bx;  o1.y = c[mf][nf][3] + by;
            if (RELU) {
                o0.x = fmaxf(o0.x, 0.f); o0.y = fmaxf(o0.y, 0.f);
                o1.x = fmaxf(o1.x, 0.f); o1.y = fmaxf(o1.y, 0.f);
            }
            if (OSPLIT) {
                __half hx, lx, hy, ly;
                split_h(o0.x, hx, lx); split_h(o0.y, hy, ly);
                *(__half2*)(Ch + (size_t)row * M + col) = __halves2half2(hx, hy);
                *(__half2*)(Cl + (size_t)row * M + col) = __halves2half2(lx, ly);
                split_h(o1.x, hx, lx); split_h(o1.y, hy, ly);
                *(__half2*)(Ch + (size_t)(row + 8) * M + col) = __halves2half2(hx, hy);
                *(__half2*)(Cl + (size_t)(row + 8) * M + col) = __halves2half2(lx, ly);
            } else {
                *(float2*)(C + (size_t)row * M + col)       = o0;
                *(float2*)(C + (size_t)(row + 8) * M + col) = o1;
            }
        }
    }
}

// ---------------- prep: cb split + csq + commit=0 --------------------------
__global__ void prep_kernel(const float* __restrict__ cb) {
    const int b = blockIdx.x;
    const int t = threadIdx.x;
    if (b < 512) {
        int idx = b * 256 + t;
        __half h, l;
        split_h(cb[idx], h, l);
        g_cbH[idx] = h;
        g_cbL[idx] = l;
    } else {
        int k = (b - 512) * 256 + t;
        if (b == 512 && t == 0) g_commit = 0.0;
        const float* row = cb + (size_t)k * CBD;
        float s = 0.f;
#pragma unroll 8
        for (int c = 0; c < CBD; c += 4) {
            float4 v = *(const float4*)(row + c);
            s += v.x*v.x + v.y*v.y + v.z*v.z + v.w*v.w;
        }
        g_csq[k] = s;
    }
}

// ---------------- split x into fp16 hi/lo planes ---------------------------
__global__ void split_x_kernel(const float* __restrict__ x) {
    size_t i = ((size_t)blockIdx.x * 256 + threadIdx.x) * 4;
    float4 v = *(const float4*)(x + i);
    __half h0, l0, h1, l1, h2, l2, h3, l3;
    split_h(v.x, h0, l0); split_h(v.y, h1, l1);
    split_h(v.z, h2, l2); split_h(v.w, h3, l3);
    *(__half2*)(g_xh + i)     = __halves2half2(h0, h1);
    *(__half2*)(g_xh + i + 2) = __halves2half2(h2, h3);
    *(__half2*)(g_xl + i)     = __halves2half2(l0, l1);
    *(__half2*)(g_xl + i + 2) = __halves2half2(l2, l3);
}

// ---------------- transpose + split: W[K,M] -> half planes [M,K] -----------
__global__ void transpose_split(const float* __restrict__ W,
                                __half* __restrict__ WTh, __half* __restrict__ WTl,
                                int K, int M) {
    int idx = blockIdx.x * 256 + threadIdx.x;
    if (idx < K * M) {
        int m = idx / K, k = idx - m * K;
        __half h, l;
        split_h(W[(size_t)k * M + m], h, l);
        WTh[idx] = h;
        WTl[idx] = l;
    }
}

// ---------------- fp32 SGEMM for the tiny decoder-table GEMMs -------------
template<bool RELU, bool HASBIAS>
__global__ void __launch_bounds__(256) sgemm_kernel(
    const float* __restrict__ A, const float* __restrict__ B,
    const float* __restrict__ bias, float* __restrict__ C,
    int N, int K, int M)
{
    __shared__ float As[16][132];
    __shared__ float Bs[16][72];
    const int tid  = threadIdx.x;
    const int tx   = tid & 15;
    const int ty   = tid >> 4;
    const int brow = blockIdx.y << 7;
    const int bcol = blockIdx.x << 6;

    const int ar = tid >> 2;
    const int ac = (tid & 3) << 2;
    const float* a0 = A + (size_t)(brow + ar) * K + ac;
    const float* a1 = A + (size_t)(brow + ar + 64) * K + ac;
    const int br = tid >> 4;
    const int bc = (tid & 15) << 2;
    const float* bptr = B + (size_t)br * M + bcol + bc;

    float acc[8][4];
#pragma unroll
    for (int i = 0; i < 8; i++)
#pragma unroll
        for (int j = 0; j < 4; j++) acc[i][j] = 0.f;

    for (int k0 = 0; k0 < K; k0 += 16) {
        float4 av0 = *(const float4*)(a0 + k0);
        float4 av1 = *(const float4*)(a1 + k0);
        float4 bv  = *(const float4*)(bptr + (size_t)k0 * M);
        As[ac + 0][ar] = av0.x;  As[ac + 1][ar] = av0.y;
        As[ac + 2][ar] = av0.z;  As[ac + 3][ar] = av0.w;
        As[ac + 0][ar + 64] = av1.x;  As[ac + 1][ar + 64] = av1.y;
        As[ac + 2][ar + 64] = av1.z;  As[ac + 3][ar + 64] = av1.w;
        *(float4*)&Bs[br][bc] = bv;
        __syncthreads();
#pragma unroll
        for (int kk = 0; kk < 16; kk++) {
            float4 a4l = *(const float4*)&As[kk][ty << 3];
            float4 a4h = *(const float4*)&As[kk][(ty << 3) + 4];
            float4 b4  = *(const float4*)&Bs[kk][tx << 2];
            float arr[8] = {a4l.x, a4l.y, a4l.z, a4l.w, a4h.x, a4h.y, a4h.z, a4h.w};
            float brr[4] = {b4.x, b4.y, b4.z, b4.w};
#pragma unroll
            for (int i = 0; i < 8; i++)
#pragma unroll
                for (int j = 0; j < 4; j++)
                    acc[i][j] = fmaf(arr[i], brr[j], acc[i][j]);
        }
        __syncthreads();
    }

    float4 bb = make_float4(0.f, 0.f, 0.f, 0.f);
    if (HASBIAS) bb = *(const float4*)(bias + bcol + (tx << 2));
#pragma unroll
    for (int i = 0; i < 8; i++) {
        float4 o;
        o.x = acc[i][0] + bb.x;
        o.y = acc[i][1] + bb.y;
        o.z = acc[i][2] + bb.z;
        o.w = acc[i][3] + bb.w;
        if (RELU) {
            o.x = fmaxf(o.x, 0.f); o.y = fmaxf(o.y, 0.f);
            o.z = fmaxf(o.z, 0.f); o.w = fmaxf(o.w, 0.f);
        }
        *(float4*)(C + (size_t)(brow + (ty << 3) + i) * M + bcol + (tx << 2)) = o;
    }
}

// ---- VQ: reduce 4 partials + commit partial + recon gather ---------------
__global__ void __launch_bounds__(256) vq_recon_kernel(
    const float2* __restrict__ part,
    const __half* __restrict__ zH, const __half* __restrict__ zL,
    const float* __restrict__ R, float* __restrict__ out_idx,
    float* __restrict__ out_recon)
{
    __shared__ float s_part[8];
    const int tid = threadIdx.x;
    const int token = (blockIdx.x << 6) + (tid >> 2);
    const int lpart = tid & 3;

    float2 e = part[(size_t)token * 4 + lpart];
    float best = e.x;
    int   bidx = (int)e.y;
#pragma unroll
    for (int off = 1; off < 4; off <<= 1) {
        float ob = __shfl_xor_sync(0xffffffffu, best, off);
        int   oi = __shfl_xor_sync(0xffffffffu, bidx, off);
        if (ob < best || (ob == best && oi < bidx)) { best = ob; bidx = oi; }
    }

    // ||z||^2 from half planes (z = zH + zL); 64 coords per lane
    const __half2* zh2 = (const __half2*)(zH + (size_t)token * CBD + (lpart << 6));
    const __half2* zl2 = (const __half2*)(zL + (size_t)token * CBD + (lpart << 6));
    float s = 0.f;
#pragma unroll
    for (int i = 0; i < 32; i++) {
        float2 a = __half22float2(zh2[i]);
        float2 b = __half22float2(zl2[i]);
        float vx = a.x + b.x, vy = a.y + b.y;
        s += vx * vx + vy * vy;
    }
    s += __shfl_xor_sync(0xffffffffu, s, 1);
    s += __shfl_xor_sync(0xffffffffu, s, 2);

    float cv = (lpart == 0) ? (s + best) : 0.f;
    if (lpart == 0) out_idx[token] = (float)bidx;

    const float4* src = (const float4*)(R + (size_t)bidx * D_IN + lpart * 192);
    float4*       dst = (float4*)(out_recon + (size_t)token * D_IN + lpart * 192);
#pragma unroll 4
    for (int i = 0; i < 48; i++) dst[i] = src[i];

#pragma unroll
    for (int off = 16; off; off >>= 1) cv += __shfl_xor_sync(0xffffffffu, cv, off);
    if ((tid & 31) == 0) s_part[tid >> 5] = cv;
    __syncthreads();
    if (tid == 0) {
        float t = 0.f;
#pragma unroll
        for (int w = 0; w < 8; w++) t += s_part[w];
        atomicAdd(&g_commit, (double)t);
    }
}

__global__ void finalize_kernel(float* __restrict__ out_loss) {
    *out_loss = (float)(g_commit * (1.0 / ((double)NTOK * CBD)));
}

// ---------------- launch ---------------------------------------------------
extern "C" void kernel_launch(void* const* d_in, const int* in_sizes, int n_in,
                              void* d_out, int out_size) {
    const float* x  = (const float*)d_in[0];
    const float* W1 = (const float*)d_in[1];
    const float* b1 = (const float*)d_in[2];
    const float* W2 = (const float*)d_in[3];
    const float* b2 = (const float*)d_in[4];
    const float* cb = (const float*)d_in[5];
    const float* W3 = (const float*)d_in[6];
    const float* b3 = (const float*)d_in[7];
    const float* W4 = (const float*)d_in[8];
    const float* b4 = (const float*)d_in[9];

    float* out       = (float*)d_out;
    float* out_recon = out;
    float* out_idx   = out + (size_t)NTOK * D_IN;
    float* out_loss  = out_idx + NTOK;

    __half *pxh, *pxl, *phH, *phL, *pzH, *pzL;
    __half *pW1TH, *pW1TL, *pW2TH, *pW2TL, *pcbH, *pcbL;
    float *pT1, *pR;
    float2* ppart;
    cudaGetSymbolAddress((void**)&pxh,   g_xh);
    cudaGetSymbolAddress((void**)&pxl,   g_xl);
    cudaGetSymbolAddress((void**)&phH,   g_hH);
    cudaGetSymbolAddress((void**)&phL,   g_hL);
    cudaGetSymbolAddress((void**)&pzH,   g_zH);
    cudaGetSymbolAddress((void**)&pzL,   g_zL);
    cudaGetSymbolAddress((void**)&ppart, g_part);
    cudaGetSymbolAddress((void**)&pT1,   g_T1);
    cudaGetSymbolAddress((void**)&pR,    g_R);
    cudaGetSymbolAddress((void**)&pW1TH, g_W1TH);
    cudaGetSymbolAddress((void**)&pW1TL, g_W1TL);
    cudaGetSymbolAddress((void**)&pW2TH, g_W2TH);
    cudaGetSymbolAddress((void**)&pW2TL, g_W2TL);
    cudaGetSymbolAddress((void**)&pcbH,  g_cbH);
    cudaGetSymbolAddress((void**)&pcbL,  g_cbL);

    static bool attr_done = false;
    if (!attr_done) {
        cudaFuncSetAttribute(hmma_gemm<true,  true,  true,  false>,
                             cudaFuncAttributeMaxDynamicSharedMemorySize, HSMEM);
        cudaFuncSetAttribute(hmma_gemm<false, true,  true,  false>,
                             cudaFuncAttributeMaxDynamicSharedMemorySize, HSMEM);
        cudaFuncSetAttribute(hmma_gemm<false, false, false, true >,
                             cudaFuncAttributeMaxDynamicSharedMemorySize, HSMEM);
        attr_done = true;
    }

    // [0] prep: cb split + csq + commit=0
    prep_kernel<<<514, 256>>>(cb);
    // [1] split x into fp16 planes
    split_x_kernel<<<(NTOK * D_IN / 4) / 256, 256>>>(x);
    // [2] W1 transpose+split
    transpose_split<<<(HID * D_IN + 255) / 256, 256>>>(W1, pW1TH, pW1TL, D_IN, HID);
    // [3] h = relu(x @ W1 + b1), split output   (ncu-captured slot)
    hmma_gemm<true,  true,  true,  false><<<dim3(HID / 128, NTOK / 128), 256, HSMEM>>>(
        pxh, pxl, pW1TH, pW1TL, b1, nullptr, phH, phL, nullptr, D_IN, HID);
    // [4] W2 transpose+split
    transpose_split<<<(CBD * HID + 255) / 256, 256>>>(W2, pW2TH, pW2TL, HID, CBD);
    // [5][6] decoder table (tiny, fp32)
    sgemm_kernel<true , true ><<<dim3(HID  / 64, 512 / 128), 256>>>(cb,  W3, b3, pT1, 512, CBD, HID);
    sgemm_kernel<false, true ><<<dim3(D_IN / 64, 512 / 128), 256>>>(pT1, W4, b4, pR,  512, HID, D_IN);
    // [7] z = h @ W2 + b2, split output
    hmma_gemm<false, true,  true,  false><<<dim3(CBD / 128, NTOK / 128), 256, HSMEM>>>(
        phH, phL, pW2TH, pW2TL, b2, nullptr, pzH, pzL, nullptr, HID, CBD);
    // [8] dots + fused argmin -> partials
    hmma_gemm<false, false, false, true ><<<dim3(CBK / 128, NTOK / 128), 256, HSMEM>>>(
        pzH, pzL, pcbH, pcbL, nullptr, nullptr, nullptr, nullptr, ppart, CBD, CBK);
    // [9] reduce partials + commit + recon gather
    vq_recon_kernel<<<NTOK / 64, 256>>>(ppart, pzH, pzL, pR, out_idx, out_recon);
    // [10] loss
    finalize_kernel<<<1, 1>>>(out_loss);
}